// round 1
// baseline (speedup 1.0000x reference)
#include <cuda_runtime.h>
#include <cstdint>
#include <cstddef>

#define NODES 100000
#define EDGES 1600000

// Scratch: __device__ globals (no allocation allowed in kernel_launch).
__device__ float g_agg1[(size_t)NODES * 128];
__device__ float g_agg2[(size_t)NODES * 128];
__device__ float g_h[(size_t)NODES * 128];
__device__ float g_deg[NODES];

// ---------------------------------------------------------------------------
// Zero the scratch buffers (needed every launch: graph replays reuse them).
// ---------------------------------------------------------------------------
__global__ void zero_kernel() {
    size_t i = (size_t)blockIdx.x * blockDim.x + threadIdx.x;
    size_t stride = (size_t)gridDim.x * blockDim.x;
    float4 z = make_float4(0.f, 0.f, 0.f, 0.f);
    float4* p1 = reinterpret_cast<float4*>(g_agg1);
    float4* p2 = reinterpret_cast<float4*>(g_agg2);
    const size_t n4 = (size_t)NODES * 128 / 4;
    for (size_t j = i; j < n4; j += stride) { p1[j] = z; p2[j] = z; }
    for (size_t j = i; j < NODES; j += stride) g_deg[j] = 0.f;
}

// ---------------------------------------------------------------------------
// Scatter-add: one warp per edge. Warp loads the 512B source feature row
// coalesced (32 x float4) and issues one red.global.add.v4.f32 per lane into
// the destination row. Optionally accumulates degree (layer 1 only).
// ---------------------------------------------------------------------------
template <bool ADD_DEG>
__global__ void scatter_kernel(const float* __restrict__ feat,
                               const int* __restrict__ esrc,
                               const int* __restrict__ edst,
                               float* __restrict__ agg,
                               int E) {
    int widx = (int)(((size_t)blockIdx.x * blockDim.x + threadIdx.x) >> 5);
    int lane = threadIdx.x & 31;
    if (widx >= E) return;
    int s = 0, d = 0;
    if (lane == 0) { s = __ldg(esrc + widx); d = __ldg(edst + widx); }
    s = __shfl_sync(0xffffffffu, s, 0);
    d = __shfl_sync(0xffffffffu, d, 0);

    float4 v = __ldg(reinterpret_cast<const float4*>(feat) + (((size_t)s) << 5) + lane);
    float* p = agg + (((size_t)d) << 7) + lane * 4;
    asm volatile("red.global.add.v4.f32 [%0], {%1, %2, %3, %4};"
                 :: "l"(p), "f"(v.x), "f"(v.y), "f"(v.z), "f"(v.w)
                 : "memory");
    if (ADD_DEG && lane == 0) atomicAdd(&g_deg[d], 1.0f);
}

// ---------------------------------------------------------------------------
// Fused SGEMM:  out[i,:] = X[i,:] @ Wr + (AGG[i,:] / max(deg[i],1)) @ Wl + b
// Treated as one K=256 GEMM; A-tile loads pick source and apply 1/deg scale.
// BM=128, BK=16, BN = full output width (128 or 64), 256 threads,
// per-thread microtile TM=8 x TN (8 or 4).
// ---------------------------------------------------------------------------
template <int BN, int TN, bool RELU>
__global__ void __launch_bounds__(256, 2) gemm_fused(
    const float* __restrict__ X,
    const float* __restrict__ AGG,
    const float* __restrict__ Wr,     // [128, BN], multiplies X
    const float* __restrict__ Wl,     // [128, BN], multiplies AGG/deg
    const float* __restrict__ bias,   // [BN]
    float* __restrict__ out,          // [N, BN]
    int N) {
    constexpr int BM = 128, BK = 16, TM = 8;
    constexpr int CG = BN / TN;        // column groups (16)
    static_assert(CG * (BM / TM) == 256, "thread layout");

    __shared__ float As[BK][BM];
    __shared__ float Bs[BK][BN];
    __shared__ float invd[BM];

    const int tid = threadIdx.x;
    const int row0 = blockIdx.x * BM;

    if (tid < BM) {
        int r = row0 + tid;
        invd[tid] = (r < N) ? (1.0f / fmaxf(g_deg[r], 1.0f)) : 0.0f;
    }

    // A-load mapping: thread -> (row am, 8 consecutive k starting at ak)
    const int am = tid >> 1;
    const int ak = (tid & 1) * 8;
    const int arow = row0 + am;

    // B-load mapping: thread -> (k row bk, BN/16 consecutive j at bj)
    const int bk = tid >> 4;
    const int bj = (tid & 15) * (BN / 16);

    // Compute mapping
    const int tx = tid % CG;
    const int ty = tid / CG;

    float bb[TN];
#pragma unroll
    for (int j = 0; j < TN; j++) bb[j] = __ldg(&bias[tx * TN + j]);

    float acc[TM][TN];
#pragma unroll
    for (int i = 0; i < TM; i++)
#pragma unroll
        for (int j = 0; j < TN; j++) acc[i][j] = 0.f;

    for (int kb = 0; kb < 256; kb += BK) {
        __syncthreads();  // previous compute done; first iter: invd ready
        // ---- load A tile (transposed into As[k][m]) ----
        float4 a0, a1;
        if (arow < N) {
            int kg = kb + ak;  // chunk of 8 never crosses the k=128 boundary
            const float* src;
            float sc;
            if (kg < 128) { src = X + (size_t)arow * 128 + kg; sc = 1.0f; }
            else          { src = AGG + (size_t)arow * 128 + (kg - 128); sc = invd[am]; }
            a0 = __ldg(reinterpret_cast<const float4*>(src));
            a1 = __ldg(reinterpret_cast<const float4*>(src) + 1);
            a0.x *= sc; a0.y *= sc; a0.z *= sc; a0.w *= sc;
            a1.x *= sc; a1.y *= sc; a1.z *= sc; a1.w *= sc;
        } else {
            a0 = make_float4(0.f, 0.f, 0.f, 0.f); a1 = a0;
        }
        As[ak + 0][am] = a0.x; As[ak + 1][am] = a0.y;
        As[ak + 2][am] = a0.z; As[ak + 3][am] = a0.w;
        As[ak + 4][am] = a1.x; As[ak + 5][am] = a1.y;
        As[ak + 6][am] = a1.z; As[ak + 7][am] = a1.w;
        // ---- load B tile ----
        {
            int kg = kb + bk;
            const float* w = (kg < 128) ? Wr : Wl;
            int kr = kg & 127;
            const float4* ws = reinterpret_cast<const float4*>(w + (size_t)kr * BN + bj);
            if (BN == 128) {
                float4 w0 = __ldg(ws), w1 = __ldg(ws + 1);
                *reinterpret_cast<float4*>(&Bs[bk][bj]) = w0;
                *reinterpret_cast<float4*>(&Bs[bk][bj + 4]) = w1;
            } else {
                float4 w0 = __ldg(ws);
                *reinterpret_cast<float4*>(&Bs[bk][bj]) = w0;
            }
        }
        __syncthreads();
        // ---- compute ----
#pragma unroll
        for (int k = 0; k < BK; k++) {
            float ar[TM];
            *reinterpret_cast<float4*>(&ar[0]) =
                *reinterpret_cast<const float4*>(&As[k][ty * TM]);
            *reinterpret_cast<float4*>(&ar[4]) =
                *reinterpret_cast<const float4*>(&As[k][ty * TM + 4]);
            float br[TN];
            *reinterpret_cast<float4*>(&br[0]) =
                *reinterpret_cast<const float4*>(&Bs[k][tx * TN]);
            if (TN == 8) {
                *reinterpret_cast<float4*>(&br[4]) =
                    *reinterpret_cast<const float4*>(&Bs[k][tx * TN + 4]);
            }
#pragma unroll
            for (int i = 0; i < TM; i++)
#pragma unroll
                for (int j = 0; j < TN; j++)
                    acc[i][j] = fmaf(ar[i], br[j], acc[i][j]);
        }
    }

    // ---- epilogue ----
#pragma unroll
    for (int i = 0; i < TM; i++) {
        int r = row0 + ty * TM + i;
        if (r < N) {
#pragma unroll
            for (int j = 0; j < TN; j += 4) {
                float4 v;
                v.x = acc[i][j + 0] + bb[j + 0];
                v.y = acc[i][j + 1] + bb[j + 1];
                v.z = acc[i][j + 2] + bb[j + 2];
                v.w = acc[i][j + 3] + bb[j + 3];
                if (RELU) {
                    v.x = fmaxf(v.x, 0.f); v.y = fmaxf(v.y, 0.f);
                    v.z = fmaxf(v.z, 0.f); v.w = fmaxf(v.w, 0.f);
                }
                *reinterpret_cast<float4*>(out + (size_t)r * BN + tx * TN + j) = v;
            }
        }
    }
}

// ---------------------------------------------------------------------------
// kernel_launch: zero -> scatter1(+deg) -> gemm1(relu) -> scatter2 -> gemm2
// ---------------------------------------------------------------------------
extern "C" void kernel_launch(void* const* d_in, const int* in_sizes, int n_in,
                              void* d_out, int out_size) {
    const float* x   = (const float*)d_in[0];
    const int*   ei  = (const int*)d_in[1];
    const float* W1l = (const float*)d_in[2];
    const float* W1r = (const float*)d_in[3];
    const float* b1  = (const float*)d_in[4];
    const float* W2l = (const float*)d_in[5];
    const float* W2r = (const float*)d_in[6];
    const float* b2  = (const float*)d_in[7];
    float* out = (float*)d_out;

    const int N = in_sizes[0] / 128;
    const int E = in_sizes[1] / 2;
    const int* esrc = ei;
    const int* edst = ei + E;

    void *p1, *p2, *ph;
    cudaGetSymbolAddress(&p1, g_agg1);
    cudaGetSymbolAddress(&p2, g_agg2);
    cudaGetSymbolAddress(&ph, g_h);
    float* agg1 = (float*)p1;
    float* agg2 = (float*)p2;
    float* h    = (float*)ph;

    zero_kernel<<<2048, 256>>>();

    const int sblocks = (int)(((long long)E * 32 + 255) / 256);
    scatter_kernel<true><<<sblocks, 256>>>(x, esrc, edst, agg1, E);

    const int gblocks = (N + 127) / 128;
    gemm_fused<128, 8, true><<<gblocks, 256>>>(x, agg1, W1r, W1l, b1, h, N);

    scatter_kernel<false><<<sblocks, 256>>>(h, esrc, edst, agg2, E);

    gemm_fused<64, 4, false><<<gblocks, 256>>>(h, agg2, W2r, W2l, b2, out, N);
}

// round 2
// speedup vs baseline: 1.2452x; 1.2452x over previous
#include <cuda_runtime.h>
#include <cstdint>
#include <cstddef>

#define NODES 100000
#define EDGES 1600000

// Scratch (__device__ globals; no allocation allowed anywhere).
__device__ float g_agg1[(size_t)NODES * 128];
__device__ float g_h[(size_t)NODES * 128];
__device__ float g_t[(size_t)NODES * 64];
__device__ int   g_count[NODES];
__device__ int   g_rowptr[NODES + 1];
__device__ int   g_cursor[NODES];
__device__ int   g_srcidx[EDGES];

// ---------------------------------------------------------------------------
// CSR build: zero counts -> histogram -> scan -> fill
// ---------------------------------------------------------------------------
__global__ void zero_count_kernel() {
    int i = blockIdx.x * blockDim.x + threadIdx.x;
    if (i < NODES) g_count[i] = 0;
}

__global__ void hist_kernel(const int* __restrict__ edst, int E) {
    int i = blockIdx.x * blockDim.x + threadIdx.x;
    if (i < E) atomicAdd(&g_count[__ldg(edst + i)], 1);
}

__global__ void scan_kernel(int E) {
    __shared__ int sums[1024];
    const int tid = threadIdx.x;
    const int CH = (NODES + 1023) / 1024;
    const int beg = tid * CH;
    const int end = min(beg + CH, NODES);
    int s = 0;
    for (int i = beg; i < end; i++) s += g_count[i];
    sums[tid] = s;
    __syncthreads();
    // inclusive Hillis-Steele scan
    for (int off = 1; off < 1024; off <<= 1) {
        int v = (tid >= off) ? sums[tid - off] : 0;
        __syncthreads();
        sums[tid] += v;
        __syncthreads();
    }
    int run = (tid == 0) ? 0 : sums[tid - 1];
    for (int i = beg; i < end; i++) {
        g_rowptr[i] = run;
        g_cursor[i] = run;
        run += g_count[i];
    }
    if (tid == 0) g_rowptr[NODES] = E;
}

__global__ void fill_kernel(const int* __restrict__ esrc,
                            const int* __restrict__ edst, int E) {
    int i = blockIdx.x * blockDim.x + threadIdx.x;
    if (i >= E) return;
    int d = __ldg(edst + i);
    int s = __ldg(esrc + i);
    int pos = atomicAdd(&g_cursor[d], 1);
    g_srcidx[pos] = s;
}

// ---------------------------------------------------------------------------
// Gather-mean, 128-wide rows: one warp per node, lane covers one float4.
// Edge-unrolled by 4 for MLP. Writes normalized mean (applies 1/deg here).
// ---------------------------------------------------------------------------
__global__ void gather128_kernel(const float* __restrict__ feat,
                                 float* __restrict__ agg, int N) {
    int w = (int)(((size_t)blockIdx.x * blockDim.x + threadIdx.x) >> 5);
    int lane = threadIdx.x & 31;
    if (w >= N) return;
    int beg = __ldg(&g_rowptr[w]);
    int end = __ldg(&g_rowptr[w + 1]);
    float4 acc = make_float4(0.f, 0.f, 0.f, 0.f);
    const float4* f4 = reinterpret_cast<const float4*>(feat);
    int e = beg;
    for (; e + 4 <= end; e += 4) {
        int s0 = __ldg(g_srcidx + e + 0);
        int s1 = __ldg(g_srcidx + e + 1);
        int s2 = __ldg(g_srcidx + e + 2);
        int s3 = __ldg(g_srcidx + e + 3);
        float4 v0 = __ldg(f4 + (((size_t)s0) << 5) + lane);
        float4 v1 = __ldg(f4 + (((size_t)s1) << 5) + lane);
        float4 v2 = __ldg(f4 + (((size_t)s2) << 5) + lane);
        float4 v3 = __ldg(f4 + (((size_t)s3) << 5) + lane);
        acc.x += (v0.x + v1.x) + (v2.x + v3.x);
        acc.y += (v0.y + v1.y) + (v2.y + v3.y);
        acc.z += (v0.z + v1.z) + (v2.z + v3.z);
        acc.w += (v0.w + v1.w) + (v2.w + v3.w);
    }
    for (; e < end; e++) {
        int s = __ldg(g_srcidx + e);
        float4 v = __ldg(f4 + (((size_t)s) << 5) + lane);
        acc.x += v.x; acc.y += v.y; acc.z += v.z; acc.w += v.w;
    }
    float inv = 1.0f / fmaxf((float)(end - beg), 1.0f);
    acc.x *= inv; acc.y *= inv; acc.z *= inv; acc.w *= inv;
    reinterpret_cast<float4*>(agg)[(((size_t)w) << 5) + lane] = acc;
}

// ---------------------------------------------------------------------------
// Gather-mean, 64-wide rows, accumulating into out (which already holds
// h@W2_r + b2). One warp per node, lane covers one float2.
// ---------------------------------------------------------------------------
__global__ void gather64_acc_kernel(const float* __restrict__ t,
                                    float* __restrict__ out, int N) {
    int w = (int)(((size_t)blockIdx.x * blockDim.x + threadIdx.x) >> 5);
    int lane = threadIdx.x & 31;
    if (w >= N) return;
    int beg = __ldg(&g_rowptr[w]);
    int end = __ldg(&g_rowptr[w + 1]);
    float2 acc = make_float2(0.f, 0.f);
    const float2* f2 = reinterpret_cast<const float2*>(t);
    int e = beg;
    for (; e + 4 <= end; e += 4) {
        int s0 = __ldg(g_srcidx + e + 0);
        int s1 = __ldg(g_srcidx + e + 1);
        int s2 = __ldg(g_srcidx + e + 2);
        int s3 = __ldg(g_srcidx + e + 3);
        float2 v0 = __ldg(f2 + (((size_t)s0) << 5) + lane);
        float2 v1 = __ldg(f2 + (((size_t)s1) << 5) + lane);
        float2 v2 = __ldg(f2 + (((size_t)s2) << 5) + lane);
        float2 v3 = __ldg(f2 + (((size_t)s3) << 5) + lane);
        acc.x += (v0.x + v1.x) + (v2.x + v3.x);
        acc.y += (v0.y + v1.y) + (v2.y + v3.y);
    }
    for (; e < end; e++) {
        int s = __ldg(g_srcidx + e);
        float2 v = __ldg(f2 + (((size_t)s) << 5) + lane);
        acc.x += v.x; acc.y += v.y;
    }
    float inv = 1.0f / fmaxf((float)(end - beg), 1.0f);
    float2* o = reinterpret_cast<float2*>(out) + (((size_t)w) << 5) + lane;
    float2 cur = *o;
    cur.x = fmaf(acc.x, inv, cur.x);
    cur.y = fmaf(acc.y, inv, cur.y);
    *o = cur;
}

// ---------------------------------------------------------------------------
// Layer-1 fused SGEMM: h = relu(X@Wr + AGG@Wl + b).  AGG pre-normalized.
// Single K=256 GEMM. BM=128, BK=16, BN=128, 256 threads, 8x8 microtile.
// ---------------------------------------------------------------------------
__global__ void __launch_bounds__(256, 2) gemm1_kernel(
    const float* __restrict__ X,
    const float* __restrict__ AGG,
    const float* __restrict__ Wr,
    const float* __restrict__ Wl,
    const float* __restrict__ bias,
    float* __restrict__ out,
    int N) {
    constexpr int BM = 128, BK = 16, BN = 128, TM = 8, TN = 8;

    __shared__ float As[BK][BM];
    __shared__ float Bs[BK][BN];

    const int tid = threadIdx.x;
    const int row0 = blockIdx.x * BM;

    const int am = tid >> 1;
    const int ak = (tid & 1) * 8;
    const int arow = row0 + am;
    const int bk = tid >> 4;
    const int bj = (tid & 15) * 8;
    const int tx = tid % 16;
    const int ty = tid / 16;

    float bb[TN];
#pragma unroll
    for (int j = 0; j < TN; j++) bb[j] = __ldg(&bias[tx * TN + j]);

    float acc[TM][TN];
#pragma unroll
    for (int i = 0; i < TM; i++)
#pragma unroll
        for (int j = 0; j < TN; j++) acc[i][j] = 0.f;

    for (int kb = 0; kb < 256; kb += BK) {
        __syncthreads();
        float4 a0, a1;
        if (arow < N) {
            int kg = kb + ak;
            const float* src = (kg < 128) ? (X + (size_t)arow * 128 + kg)
                                          : (AGG + (size_t)arow * 128 + (kg - 128));
            a0 = __ldg(reinterpret_cast<const float4*>(src));
            a1 = __ldg(reinterpret_cast<const float4*>(src) + 1);
        } else {
            a0 = make_float4(0.f, 0.f, 0.f, 0.f); a1 = a0;
        }
        As[ak + 0][am] = a0.x; As[ak + 1][am] = a0.y;
        As[ak + 2][am] = a0.z; As[ak + 3][am] = a0.w;
        As[ak + 4][am] = a1.x; As[ak + 5][am] = a1.y;
        As[ak + 6][am] = a1.z; As[ak + 7][am] = a1.w;
        {
            int kg = kb + bk;
            const float* w = (kg < 128) ? Wr : Wl;
            int kr = kg & 127;
            const float4* ws = reinterpret_cast<const float4*>(w + (size_t)kr * 128 + bj);
            float4 w0 = __ldg(ws), w1 = __ldg(ws + 1);
            *reinterpret_cast<float4*>(&Bs[bk][bj]) = w0;
            *reinterpret_cast<float4*>(&Bs[bk][bj + 4]) = w1;
        }
        __syncthreads();
#pragma unroll
        for (int k = 0; k < BK; k++) {
            float ar[TM], br[TN];
            *reinterpret_cast<float4*>(&ar[0]) =
                *reinterpret_cast<const float4*>(&As[k][ty * TM]);
            *reinterpret_cast<float4*>(&ar[4]) =
                *reinterpret_cast<const float4*>(&As[k][ty * TM + 4]);
            *reinterpret_cast<float4*>(&br[0]) =
                *reinterpret_cast<const float4*>(&Bs[k][tx * TN]);
            *reinterpret_cast<float4*>(&br[4]) =
                *reinterpret_cast<const float4*>(&Bs[k][tx * TN + 4]);
#pragma unroll
            for (int i = 0; i < TM; i++)
#pragma unroll
                for (int j = 0; j < TN; j++)
                    acc[i][j] = fmaf(ar[i], br[j], acc[i][j]);
        }
    }

#pragma unroll
    for (int i = 0; i < TM; i++) {
        int r = row0 + ty * TM + i;
        if (r < N) {
#pragma unroll
            for (int j = 0; j < TN; j += 4) {
                float4 v;
                v.x = fmaxf(acc[i][j + 0] + bb[j + 0], 0.f);
                v.y = fmaxf(acc[i][j + 1] + bb[j + 1], 0.f);
                v.z = fmaxf(acc[i][j + 2] + bb[j + 2], 0.f);
                v.w = fmaxf(acc[i][j + 3] + bb[j + 3], 0.f);
                *reinterpret_cast<float4*>(out + (size_t)r * 128 + tx * TN + j) = v;
            }
        }
    }
}

// ---------------------------------------------------------------------------
// Layer-2 dual GEMM: out_partial = H@Wr + b (cols 0..63 of the virtual BN=128)
//                    t           = H@Wl     (cols 64..127)
// K=128. BM=128, BK=16, BN=128, 256 threads, 8x8 microtile.
// ---------------------------------------------------------------------------
__global__ void __launch_bounds__(256, 2) gemm2_dual_kernel(
    const float* __restrict__ H,
    const float* __restrict__ Wr,
    const float* __restrict__ Wl,
    const float* __restrict__ bias,
    float* __restrict__ out,
    float* __restrict__ t,
    int N) {
    constexpr int BM = 128, BK = 16, TM = 8, TN = 8;

    __shared__ float As[BK][BM];
    __shared__ float Bs[BK][128];

    const int tid = threadIdx.x;
    const int row0 = blockIdx.x * BM;

    const int am = tid >> 1;
    const int ak = (tid & 1) * 8;
    const int arow = row0 + am;
    const int bk = tid >> 4;
    const int bj = (tid & 15) * 8;
    const int tx = tid % 16;
    const int ty = tid / 16;

    float bb[TN];
#pragma unroll
    for (int j = 0; j < TN; j++)
        bb[j] = (tx < 8) ? __ldg(&bias[tx * TN + j]) : 0.f;

    float acc[TM][TN];
#pragma unroll
    for (int i = 0; i < TM; i++)
#pragma unroll
        for (int j = 0; j < TN; j++) acc[i][j] = 0.f;

    for (int kb = 0; kb < 128; kb += BK) {
        __syncthreads();
        float4 a0, a1;
        if (arow < N) {
            const float* src = H + (size_t)arow * 128 + kb + ak;
            a0 = __ldg(reinterpret_cast<const float4*>(src));
            a1 = __ldg(reinterpret_cast<const float4*>(src) + 1);
        } else {
            a0 = make_float4(0.f, 0.f, 0.f, 0.f); a1 = a0;
        }
        As[ak + 0][am] = a0.x; As[ak + 1][am] = a0.y;
        As[ak + 2][am] = a0.z; As[ak + 3][am] = a0.w;
        As[ak + 4][am] = a1.x; As[ak + 5][am] = a1.y;
        As[ak + 6][am] = a1.z; As[ak + 7][am] = a1.w;
        {
            int kr = kb + bk;
            const float* w = (bj < 64) ? (Wr + (size_t)kr * 64 + bj)
                                       : (Wl + (size_t)kr * 64 + (bj - 64));
            float4 w0 = __ldg(reinterpret_cast<const float4*>(w));
            float4 w1 = __ldg(reinterpret_cast<const float4*>(w) + 1);
            *reinterpret_cast<float4*>(&Bs[bk][bj]) = w0;
            *reinterpret_cast<float4*>(&Bs[bk][bj + 4]) = w1;
        }
        __syncthreads();
#pragma unroll
        for (int k = 0; k < BK; k++) {
            float ar[TM], br[TN];
            *reinterpret_cast<float4*>(&ar[0]) =
                *reinterpret_cast<const float4*>(&As[k][ty * TM]);
            *reinterpret_cast<float4*>(&ar[4]) =
                *reinterpret_cast<const float4*>(&As[k][ty * TM + 4]);
            *reinterpret_cast<float4*>(&br[0]) =
                *reinterpret_cast<const float4*>(&Bs[k][tx * TN]);
            *reinterpret_cast<float4*>(&br[4]) =
                *reinterpret_cast<const float4*>(&Bs[k][tx * TN + 4]);
#pragma unroll
            for (int i = 0; i < TM; i++)
#pragma unroll
                for (int j = 0; j < TN; j++)
                    acc[i][j] = fmaf(ar[i], br[j], acc[i][j]);
        }
    }

#pragma unroll
    for (int i = 0; i < TM; i++) {
        int r = row0 + ty * TM + i;
        if (r < N) {
            float* dst = (tx < 8) ? (out + (size_t)r * 64 + tx * TN)
                                  : (t + (size_t)r * 64 + (tx - 8) * TN);
#pragma unroll
            for (int j = 0; j < TN; j += 4) {
                float4 v;
                v.x = acc[i][j + 0] + bb[j + 0];
                v.y = acc[i][j + 1] + bb[j + 1];
                v.z = acc[i][j + 2] + bb[j + 2];
                v.w = acc[i][j + 3] + bb[j + 3];
                *reinterpret_cast<float4*>(dst + j) = v;
            }
        }
    }
}

// ---------------------------------------------------------------------------
// kernel_launch
// ---------------------------------------------------------------------------
extern "C" void kernel_launch(void* const* d_in, const int* in_sizes, int n_in,
                              void* d_out, int out_size) {
    const float* x   = (const float*)d_in[0];
    const int*   ei  = (const int*)d_in[1];
    const float* W1l = (const float*)d_in[2];
    const float* W1r = (const float*)d_in[3];
    const float* b1  = (const float*)d_in[4];
    const float* W2l = (const float*)d_in[5];
    const float* W2r = (const float*)d_in[6];
    const float* b2  = (const float*)d_in[7];
    float* out = (float*)d_out;

    const int N = in_sizes[0] / 128;
    const int E = in_sizes[1] / 2;
    const int* esrc = ei;
    const int* edst = ei + E;

    void *p1, *ph, *pt;
    cudaGetSymbolAddress(&p1, g_agg1);
    cudaGetSymbolAddress(&ph, g_h);
    cudaGetSymbolAddress(&pt, g_t);
    float* agg1 = (float*)p1;
    float* h    = (float*)ph;
    float* t    = (float*)pt;

    // CSR build
    zero_count_kernel<<<(NODES + 255) / 256, 256>>>();
    hist_kernel<<<(E + 255) / 256, 256>>>(edst, E);
    scan_kernel<<<1, 1024>>>(E);
    fill_kernel<<<(E + 255) / 256, 256>>>(esrc, edst, E);

    const int wblocks = (N * 32 + 255) / 256;
    const int gblocks = (N + 127) / 128;

    // Layer 1
    gather128_kernel<<<wblocks, 256>>>(x, agg1, N);
    gemm1_kernel<<<gblocks, 256>>>(x, agg1, W1r, W1l, b1, h, N);

    // Layer 2: transform first, then aggregate the 64-wide t
    gemm2_dual_kernel<<<gblocks, 256>>>(h, W2r, W2l, b2, out, t, N);
    gather64_acc_kernel<<<wblocks, 256>>>(t, out, N);
}

// round 3
// speedup vs baseline: 1.3718x; 1.1017x over previous
#include <cuda_runtime.h>
#include <cstdint>
#include <cstddef>

#define NODES 100000
#define EDGES 1600000

// Scratch (__device__ globals; no allocation allowed anywhere).
__device__ float g_p1[(size_t)NODES * 128];   // layer1: x@W1_r ; layer2: p2/t2 (N*64 each)
__device__ float g_t1[(size_t)NODES * 128];   // layer1: x@W1_l
__device__ float g_h[(size_t)NODES * 128];
__device__ int   g_count[NODES];
__device__ int   g_rowptr[NODES + 1];
__device__ int   g_cursor[NODES];
__device__ int   g_srcidx[EDGES];

// ---------------------------------------------------------------------------
// CSR build: zero counts -> histogram -> scan -> fill
// ---------------------------------------------------------------------------
__global__ void zero_count_kernel() {
    int i = blockIdx.x * blockDim.x + threadIdx.x;
    if (i < NODES) g_count[i] = 0;
}

__global__ void hist_kernel(const int* __restrict__ edst, int E) {
    int i = blockIdx.x * blockDim.x + threadIdx.x;
    if (i < E) atomicAdd(&g_count[__ldg(edst + i)], 1);
}

__global__ void scan_kernel(int E) {
    __shared__ int sums[1024];
    const int tid = threadIdx.x;
    const int CH = (NODES + 1023) / 1024;
    const int beg = tid * CH;
    const int end = min(beg + CH, NODES);
    int s = 0;
    for (int i = beg; i < end; i++) s += g_count[i];
    sums[tid] = s;
    __syncthreads();
    for (int off = 1; off < 1024; off <<= 1) {
        int v = (tid >= off) ? sums[tid - off] : 0;
        __syncthreads();
        sums[tid] += v;
        __syncthreads();
    }
    int run = (tid == 0) ? 0 : sums[tid - 1];
    for (int i = beg; i < end; i++) {
        g_rowptr[i] = run;
        g_cursor[i] = run;
        run += g_count[i];
    }
    if (tid == 0) g_rowptr[NODES] = E;
}

__global__ void fill_kernel(const int* __restrict__ esrc,
                            const int* __restrict__ edst, int E) {
    int i = blockIdx.x * blockDim.x + threadIdx.x;
    if (i >= E) return;
    int d = __ldg(edst + i);
    int s = __ldg(esrc + i);
    int pos = atomicAdd(&g_cursor[d], 1);
    g_srcidx[pos] = s;
}

// ---------------------------------------------------------------------------
// TF32x3 tensor-core GEMM.
//   C[M x 2*bcols] = A[M x 128] @ [B0 | B1]   (each B is [128 x bcols] row-major)
//   Output column j < bcols -> out0[row*bcols + j], else out1[row*bcols + j-bcols].
// BM=128, BN=128 per CTA, full K=128 resident in smem. 8 warps (4x2),
// 32x64 warp tile, mma.sync.m16n8k8 tf32 with hi/lo split (3 MMAs/tile).
// ---------------------------------------------------------------------------
#define GEMM_SMEM_BYTES (2 * 128 * 132 * 4)

__device__ __forceinline__ void split_tf32(float v, uint32_t& hi, uint32_t& lo) {
    uint32_t h;
    asm("cvt.rna.tf32.f32 %0, %1;" : "=r"(h) : "f"(v));
    float l = v - __uint_as_float(h);
    uint32_t lw;
    asm("cvt.rna.tf32.f32 %0, %1;" : "=r"(lw) : "f"(l));
    hi = h; lo = lw;
}

__device__ __forceinline__ void mma_tf32(float c[4], const uint32_t a[4],
                                         const uint32_t b[2]) {
    asm volatile(
        "mma.sync.aligned.m16n8k8.row.col.f32.tf32.tf32.f32 "
        "{%0,%1,%2,%3}, {%4,%5,%6,%7}, {%8,%9}, {%0,%1,%2,%3};"
        : "+f"(c[0]), "+f"(c[1]), "+f"(c[2]), "+f"(c[3])
        : "r"(a[0]), "r"(a[1]), "r"(a[2]), "r"(a[3]), "r"(b[0]), "r"(b[1]));
}

__global__ void __launch_bounds__(256, 1) gemm_tc(
    const float* __restrict__ A,
    const float* __restrict__ B0,
    const float* __restrict__ B1,
    float* __restrict__ out0,
    float* __restrict__ out1,
    int bcols, int Nrows) {
    extern __shared__ float smem[];
    float* As = smem;                 // [128][132] row-major (m, k)
    float* Bs = smem + 128 * 132;     // [128][132] row-major (k, n)

    const int tid = threadIdx.x;
    const int row0 = blockIdx.x * 128;
    const int by = blockIdx.y;

    // ---- load A tile ----
#pragma unroll
    for (int i = 0; i < 16; i++) {
        int l = tid + i * 256;
        int r = l >> 5;
        int c4 = (l & 31) * 4;
        float4 v = make_float4(0.f, 0.f, 0.f, 0.f);
        int gr = row0 + r;
        if (gr < Nrows)
            v = __ldg(reinterpret_cast<const float4*>(A + (size_t)gr * 128 + c4));
        *reinterpret_cast<float4*>(&As[r * 132 + c4]) = v;
    }
    // ---- load B tile (cols [by*128, by*128+128) of virtual [B0|B1]) ----
#pragma unroll
    for (int i = 0; i < 16; i++) {
        int l = tid + i * 256;
        int k = l >> 5;
        int n4 = (l & 31) * 4;
        int jg = by * 128 + n4;
        int sel = jg >= bcols;
        const float* src = sel ? B1 : B0;
        float4 v = __ldg(reinterpret_cast<const float4*>(
            src + (size_t)k * bcols + (jg - sel * bcols)));
        *reinterpret_cast<float4*>(&Bs[k * 132 + n4]) = v;
    }
    __syncthreads();

    const int wid = tid >> 5;
    const int lane = tid & 31;
    const int gid = lane >> 2;
    const int tig = lane & 3;
    const int wm = (wid & 3) * 32;   // warp m-base
    const int wn = (wid >> 2) * 64;  // warp n-base

    float acc[2][8][4];
#pragma unroll
    for (int mt = 0; mt < 2; mt++)
#pragma unroll
        for (int nt = 0; nt < 8; nt++)
#pragma unroll
            for (int q = 0; q < 4; q++) acc[mt][nt][q] = 0.f;

#pragma unroll 2
    for (int ks = 0; ks < 16; ks++) {
        const int kb = ks * 8;
        uint32_t ah[2][4], al[2][4];
#pragma unroll
        for (int mt = 0; mt < 2; mt++) {
            int mb = wm + mt * 16;
            float a0 = As[(mb + gid) * 132 + kb + tig];
            float a1 = As[(mb + gid + 8) * 132 + kb + tig];
            float a2 = As[(mb + gid) * 132 + kb + tig + 4];
            float a3 = As[(mb + gid + 8) * 132 + kb + tig + 4];
            split_tf32(a0, ah[mt][0], al[mt][0]);
            split_tf32(a1, ah[mt][1], al[mt][1]);
            split_tf32(a2, ah[mt][2], al[mt][2]);
            split_tf32(a3, ah[mt][3], al[mt][3]);
        }
        uint32_t bh[8][2], bl[8][2];
#pragma unroll
        for (int nt = 0; nt < 8; nt++) {
            int n = wn + nt * 8 + gid;
            float b0 = Bs[(kb + tig) * 132 + n];
            float b1 = Bs[(kb + tig + 4) * 132 + n];
            split_tf32(b0, bh[nt][0], bl[nt][0]);
            split_tf32(b1, bh[nt][1], bl[nt][1]);
        }
#pragma unroll
        for (int mt = 0; mt < 2; mt++)
#pragma unroll
            for (int nt = 0; nt < 8; nt++) {
                mma_tf32(acc[mt][nt], ah[mt], bh[nt]);
                mma_tf32(acc[mt][nt], al[mt], bh[nt]);
                mma_tf32(acc[mt][nt], ah[mt], bl[nt]);
            }
    }

    // ---- epilogue ----
#pragma unroll
    for (int mt = 0; mt < 2; mt++) {
#pragma unroll
        for (int nt = 0; nt < 8; nt++) {
            int jg = by * 128 + wn + nt * 8 + 2 * tig;
            int sel = jg >= bcols;
            float* o = sel ? out1 : out0;
            int col = jg - sel * bcols;
            int m0 = row0 + wm + mt * 16 + gid;
            int m1 = m0 + 8;
            if (m0 < Nrows) {
                float2 v = make_float2(acc[mt][nt][0], acc[mt][nt][1]);
                *reinterpret_cast<float2*>(o + (size_t)m0 * bcols + col) = v;
            }
            if (m1 < Nrows) {
                float2 v = make_float2(acc[mt][nt][2], acc[mt][nt][3]);
                *reinterpret_cast<float2*>(o + (size_t)m1 * bcols + col) = v;
            }
        }
    }
}

// ---------------------------------------------------------------------------
// Fused gather epilogues (one warp per node).
// Layer1: h = relu(p1 + b1 + mean(t1[src]))       (128-wide, float4/lane)
// Layer2: out = p2 + b2 + mean(t2[src])           (64-wide, float2/lane)
// ---------------------------------------------------------------------------
__global__ void gather_relu_kernel(const float* __restrict__ t1,
                                   const float* __restrict__ p1,
                                   const float* __restrict__ bias,
                                   float* __restrict__ h, int N) {
    int w = (int)(((size_t)blockIdx.x * blockDim.x + threadIdx.x) >> 5);
    int lane = threadIdx.x & 31;
    if (w >= N) return;
    int beg = __ldg(&g_rowptr[w]);
    int end = __ldg(&g_rowptr[w + 1]);
    float4 acc = make_float4(0.f, 0.f, 0.f, 0.f);
    const float4* f4 = reinterpret_cast<const float4*>(t1);
    int e = beg;
    for (; e + 4 <= end; e += 4) {
        int s0 = __ldg(g_srcidx + e + 0);
        int s1 = __ldg(g_srcidx + e + 1);
        int s2 = __ldg(g_srcidx + e + 2);
        int s3 = __ldg(g_srcidx + e + 3);
        float4 v0 = __ldg(f4 + (((size_t)s0) << 5) + lane);
        float4 v1 = __ldg(f4 + (((size_t)s1) << 5) + lane);
        float4 v2 = __ldg(f4 + (((size_t)s2) << 5) + lane);
        float4 v3 = __ldg(f4 + (((size_t)s3) << 5) + lane);
        acc.x += (v0.x + v1.x) + (v2.x + v3.x);
        acc.y += (v0.y + v1.y) + (v2.y + v3.y);
        acc.z += (v0.z + v1.z) + (v2.z + v3.z);
        acc.w += (v0.w + v1.w) + (v2.w + v3.w);
    }
    for (; e < end; e++) {
        int s = __ldg(g_srcidx + e);
        float4 v = __ldg(f4 + (((size_t)s) << 5) + lane);
        acc.x += v.x; acc.y += v.y; acc.z += v.z; acc.w += v.w;
    }
    float inv = 1.0f / fmaxf((float)(end - beg), 1.0f);
    float4 p = __ldg(reinterpret_cast<const float4*>(p1) + (((size_t)w) << 5) + lane);
    float4 b = __ldg(reinterpret_cast<const float4*>(bias) + lane);
    float4 r;
    r.x = fmaxf(fmaf(acc.x, inv, p.x + b.x), 0.f);
    r.y = fmaxf(fmaf(acc.y, inv, p.y + b.y), 0.f);
    r.z = fmaxf(fmaf(acc.z, inv, p.z + b.z), 0.f);
    r.w = fmaxf(fmaf(acc.w, inv, p.w + b.w), 0.f);
    reinterpret_cast<float4*>(h)[(((size_t)w) << 5) + lane] = r;
}

__global__ void gather_add_kernel(const float* __restrict__ t2,
                                  const float* __restrict__ p2,
                                  const float* __restrict__ bias,
                                  float* __restrict__ out, int N) {
    int w = (int)(((size_t)blockIdx.x * blockDim.x + threadIdx.x) >> 5);
    int lane = threadIdx.x & 31;
    if (w >= N) return;
    int beg = __ldg(&g_rowptr[w]);
    int end = __ldg(&g_rowptr[w + 1]);
    float2 acc = make_float2(0.f, 0.f);
    const float2* f2 = reinterpret_cast<const float2*>(t2);
    int e = beg;
    for (; e + 4 <= end; e += 4) {
        int s0 = __ldg(g_srcidx + e + 0);
        int s1 = __ldg(g_srcidx + e + 1);
        int s2 = __ldg(g_srcidx + e + 2);
        int s3 = __ldg(g_srcidx + e + 3);
        float2 v0 = __ldg(f2 + (((size_t)s0) << 5) + lane);
        float2 v1 = __ldg(f2 + (((size_t)s1) << 5) + lane);
        float2 v2 = __ldg(f2 + (((size_t)s2) << 5) + lane);
        float2 v3 = __ldg(f2 + (((size_t)s3) << 5) + lane);
        acc.x += (v0.x + v1.x) + (v2.x + v3.x);
        acc.y += (v0.y + v1.y) + (v2.y + v3.y);
    }
    for (; e < end; e++) {
        int s = __ldg(g_srcidx + e);
        float2 v = __ldg(f2 + (((size_t)s) << 5) + lane);
        acc.x += v.x; acc.y += v.y;
    }
    float inv = 1.0f / fmaxf((float)(end - beg), 1.0f);
    float2 p = __ldg(reinterpret_cast<const float2*>(p2) + (((size_t)w) << 5) + lane);
    float2 b = __ldg(reinterpret_cast<const float2*>(bias) + lane);
    float2 r;
    r.x = fmaf(acc.x, inv, p.x + b.x);
    r.y = fmaf(acc.y, inv, p.y + b.y);
    reinterpret_cast<float2*>(out)[(((size_t)w) << 5) + lane] = r;
}

// ---------------------------------------------------------------------------
// kernel_launch
// ---------------------------------------------------------------------------
extern "C" void kernel_launch(void* const* d_in, const int* in_sizes, int n_in,
                              void* d_out, int out_size) {
    const float* x   = (const float*)d_in[0];
    const int*   ei  = (const int*)d_in[1];
    const float* W1l = (const float*)d_in[2];
    const float* W1r = (const float*)d_in[3];
    const float* b1  = (const float*)d_in[4];
    const float* W2l = (const float*)d_in[5];
    const float* W2r = (const float*)d_in[6];
    const float* b2  = (const float*)d_in[7];
    float* out = (float*)d_out;

    const int N = in_sizes[0] / 128;
    const int E = in_sizes[1] / 2;
    const int* esrc = ei;
    const int* edst = ei + E;

    void *pp1, *pt1, *ph;
    cudaGetSymbolAddress(&pp1, g_p1);
    cudaGetSymbolAddress(&pt1, g_t1);
    cudaGetSymbolAddress(&ph, g_h);
    float* p1 = (float*)pp1;
    float* t1 = (float*)pt1;
    float* h  = (float*)ph;
    float* p2 = p1;                       // reuse (N*64)
    float* t2 = t1;                       // reuse (N*64)

    cudaFuncSetAttribute(gemm_tc, cudaFuncAttributeMaxDynamicSharedMemorySize,
                         GEMM_SMEM_BYTES);

    // CSR build
    zero_count_kernel<<<(NODES + 255) / 256, 256>>>();
    hist_kernel<<<(E + 255) / 256, 256>>>(edst, E);
    scan_kernel<<<1, 1024>>>(E);
    fill_kernel<<<(E + 255) / 256, 256>>>(esrc, edst, E);

    const int wblocks = (N * 32 + 255) / 256;
    const int gx = (N + 127) / 128;

    // Layer 1: [p1|t1] = x @ [W1_r | W1_l], then gather+relu
    gemm_tc<<<dim3(gx, 2), 256, GEMM_SMEM_BYTES>>>(x, W1r, W1l, p1, t1, 128, N);
    gather_relu_kernel<<<wblocks, 256>>>(t1, p1, b1, h, N);

    // Layer 2: [p2|t2] = h @ [W2_r | W2_l], then gather+add
    gemm_tc<<<dim3(gx, 1), 256, GEMM_SMEM_BYTES>>>(h, W2r, W2l, p2, t2, 64, N);
    gather_add_kernel<<<wblocks, 256>>>(t2, p2, b2, out, N);
}

// round 4
// speedup vs baseline: 1.3980x; 1.0191x over previous
#include <cuda_runtime.h>
#include <cstdint>
#include <cstddef>

#define NODES 100000
#define EDGES 1600000

// Scratch (__device__ globals; no allocation allowed anywhere).
__device__ float g_p1[(size_t)NODES * 128];   // layer1: x@W1_r ; layer2: p2 (N*64)
__device__ float g_t1[(size_t)NODES * 128];   // layer1: x@W1_l ; layer2: t2 (N*64)
__device__ float g_h[(size_t)NODES * 128];
__device__ int   g_count[NODES];
__device__ int   g_rowptr[NODES + 1];
__device__ int   g_cursor[NODES];
__device__ int   g_srcidx[EDGES];

// ---------------------------------------------------------------------------
// CSR build: zero counts -> histogram -> scan -> fill
// ---------------------------------------------------------------------------
__global__ void zero_count_kernel() {
    int i = blockIdx.x * blockDim.x + threadIdx.x;
    if (i < NODES) g_count[i] = 0;
}

__global__ void hist_kernel(const int* __restrict__ edst, int E) {
    int i = blockIdx.x * blockDim.x + threadIdx.x;
    if (i < E) atomicAdd(&g_count[__ldg(edst + i)], 1);
}

__global__ void scan_kernel(int E) {
    __shared__ int sums[1024];
    const int tid = threadIdx.x;
    const int CH = (NODES + 1023) / 1024;
    const int beg = tid * CH;
    const int end = min(beg + CH, NODES);
    int s = 0;
    for (int i = beg; i < end; i++) s += g_count[i];
    sums[tid] = s;
    __syncthreads();
    for (int off = 1; off < 1024; off <<= 1) {
        int v = (tid >= off) ? sums[tid - off] : 0;
        __syncthreads();
        sums[tid] += v;
        __syncthreads();
    }
    int run = (tid == 0) ? 0 : sums[tid - 1];
    for (int i = beg; i < end; i++) {
        g_rowptr[i] = run;
        g_cursor[i] = run;
        run += g_count[i];
    }
    if (tid == 0) g_rowptr[NODES] = E;
}

__global__ void fill_kernel(const int* __restrict__ esrc,
                            const int* __restrict__ edst, int E) {
    int i = blockIdx.x * blockDim.x + threadIdx.x;
    if (i >= E) return;
    int d = __ldg(edst + i);
    int s = __ldg(esrc + i);
    int pos = atomicAdd(&g_cursor[d], 1);
    g_srcidx[pos] = s;
}

// ---------------------------------------------------------------------------
// TF32x3 tensor-core GEMM.  C[M x 2*bcols] = A[M x 128] @ [B0 | B1].
// B is pre-split into TF32 hi/lo in smem at load time; A split in registers.
// BM=128, BN=128, full K=128 resident. 8 warps (4x2), 32x64 warp tiles.
// ---------------------------------------------------------------------------
#define GEMM_SMEM_BYTES (3 * 128 * 132 * 4)

__device__ __forceinline__ void split_tf32(float v, uint32_t& hi, uint32_t& lo) {
    uint32_t h;
    asm("cvt.rna.tf32.f32 %0, %1;" : "=r"(h) : "f"(v));
    float l = v - __uint_as_float(h);
    uint32_t lw;
    asm("cvt.rna.tf32.f32 %0, %1;" : "=r"(lw) : "f"(l));
    hi = h; lo = lw;
}

__device__ __forceinline__ void mma_tf32(float c[4], const uint32_t a[4],
                                         const uint32_t b[2]) {
    asm volatile(
        "mma.sync.aligned.m16n8k8.row.col.f32.tf32.tf32.f32 "
        "{%0,%1,%2,%3}, {%4,%5,%6,%7}, {%8,%9}, {%0,%1,%2,%3};"
        : "+f"(c[0]), "+f"(c[1]), "+f"(c[2]), "+f"(c[3])
        : "r"(a[0]), "r"(a[1]), "r"(a[2]), "r"(a[3]), "r"(b[0]), "r"(b[1]));
}

__global__ void __launch_bounds__(256, 1) gemm_tc(
    const float* __restrict__ A,
    const float* __restrict__ B0,
    const float* __restrict__ B1,
    float* __restrict__ out0,
    float* __restrict__ out1,
    int bcols, int Nrows) {
    extern __shared__ float smem[];
    float*    As = smem;                                    // [128][132] (m, k)
    uint32_t* Bh = reinterpret_cast<uint32_t*>(smem + 128 * 132);  // [128][132] (k, n)
    uint32_t* Bl = Bh + 128 * 132;

    const int tid = threadIdx.x;
    const int row0 = blockIdx.x * 128;
    const int by = blockIdx.y;

    // ---- load A tile ----
#pragma unroll
    for (int i = 0; i < 16; i++) {
        int l = tid + i * 256;
        int r = l >> 5;
        int c4 = (l & 31) * 4;
        float4 v = make_float4(0.f, 0.f, 0.f, 0.f);
        int gr = row0 + r;
        if (gr < Nrows)
            v = __ldg(reinterpret_cast<const float4*>(A + (size_t)gr * 128 + c4));
        *reinterpret_cast<float4*>(&As[r * 132 + c4]) = v;
    }
    // ---- load + pre-split B tile ----
#pragma unroll
    for (int i = 0; i < 16; i++) {
        int l = tid + i * 256;
        int k = l >> 5;
        int n4 = (l & 31) * 4;
        int jg = by * 128 + n4;
        int sel = jg >= bcols;
        const float* src = sel ? B1 : B0;
        float4 v = __ldg(reinterpret_cast<const float4*>(
            src + (size_t)k * bcols + (jg - sel * bcols)));
        uint32_t h0, l0, h1, l1, h2, l2, h3, l3;
        split_tf32(v.x, h0, l0); split_tf32(v.y, h1, l1);
        split_tf32(v.z, h2, l2); split_tf32(v.w, h3, l3);
        int o = k * 132 + n4;
        Bh[o + 0] = h0; Bh[o + 1] = h1; Bh[o + 2] = h2; Bh[o + 3] = h3;
        Bl[o + 0] = l0; Bl[o + 1] = l1; Bl[o + 2] = l2; Bl[o + 3] = l3;
    }
    __syncthreads();

    const int wid = tid >> 5;
    const int lane = tid & 31;
    const int gid = lane >> 2;
    const int tig = lane & 3;
    const int wm = (wid & 3) * 32;   // warp m-base
    const int wn = (wid >> 2) * 64;  // warp n-base

    float acc[2][8][4];
#pragma unroll
    for (int mt = 0; mt < 2; mt++)
#pragma unroll
        for (int nt = 0; nt < 8; nt++)
#pragma unroll
            for (int q = 0; q < 4; q++) acc[mt][nt][q] = 0.f;

#pragma unroll 2
    for (int ks = 0; ks < 16; ks++) {
        const int kb = ks * 8;
        uint32_t ah[2][4], al[2][4];
#pragma unroll
        for (int mt = 0; mt < 2; mt++) {
            int mb = wm + mt * 16;
            float a0 = As[(mb + gid) * 132 + kb + tig];
            float a1 = As[(mb + gid + 8) * 132 + kb + tig];
            float a2 = As[(mb + gid) * 132 + kb + tig + 4];
            float a3 = As[(mb + gid + 8) * 132 + kb + tig + 4];
            split_tf32(a0, ah[mt][0], al[mt][0]);
            split_tf32(a1, ah[mt][1], al[mt][1]);
            split_tf32(a2, ah[mt][2], al[mt][2]);
            split_tf32(a3, ah[mt][3], al[mt][3]);
        }
        uint32_t bh[8][2], bl[8][2];
#pragma unroll
        for (int nt = 0; nt < 8; nt++) {
            int n = wn + nt * 8 + gid;
            bh[nt][0] = Bh[(kb + tig) * 132 + n];
            bh[nt][1] = Bh[(kb + tig + 4) * 132 + n];
            bl[nt][0] = Bl[(kb + tig) * 132 + n];
            bl[nt][1] = Bl[(kb + tig + 4) * 132 + n];
        }
#pragma unroll
        for (int mt = 0; mt < 2; mt++)
#pragma unroll
            for (int nt = 0; nt < 8; nt++) {
                mma_tf32(acc[mt][nt], ah[mt], bh[nt]);
                mma_tf32(acc[mt][nt], al[mt], bh[nt]);
                mma_tf32(acc[mt][nt], ah[mt], bl[nt]);
            }
    }

    // ---- epilogue ----
#pragma unroll
    for (int mt = 0; mt < 2; mt++) {
#pragma unroll
        for (int nt = 0; nt < 8; nt++) {
            int jg = by * 128 + wn + nt * 8 + 2 * tig;
            int sel = jg >= bcols;
            float* o = sel ? out1 : out0;
            int col = jg - sel * bcols;
            int m0 = row0 + wm + mt * 16 + gid;
            int m1 = m0 + 8;
            if (m0 < Nrows) {
                float2 v = make_float2(acc[mt][nt][0], acc[mt][nt][1]);
                *reinterpret_cast<float2*>(o + (size_t)m0 * bcols + col) = v;
            }
            if (m1 < Nrows) {
                float2 v = make_float2(acc[mt][nt][2], acc[mt][nt][3]);
                *reinterpret_cast<float2*>(o + (size_t)m1 * bcols + col) = v;
            }
        }
    }
}

// ---------------------------------------------------------------------------
// Fused gather epilogues (one warp per node, edge-unrolled by 8).
// Layer1: h = relu(p1 + b1 + mean(t1[src]))       (128-wide, float4/lane)
// Layer2: out = p2 + b2 + mean(t2[src])           (64-wide, float2/lane)
// ---------------------------------------------------------------------------
__global__ void gather_relu_kernel(const float* __restrict__ t1,
                                   const float* __restrict__ p1,
                                   const float* __restrict__ bias,
                                   float* __restrict__ h, int N) {
    int w = (int)(((size_t)blockIdx.x * blockDim.x + threadIdx.x) >> 5);
    int lane = threadIdx.x & 31;
    if (w >= N) return;
    int beg = __ldg(&g_rowptr[w]);
    int end = __ldg(&g_rowptr[w + 1]);
    float4 acc = make_float4(0.f, 0.f, 0.f, 0.f);
    const float4* f4 = reinterpret_cast<const float4*>(t1);
    int e = beg;
    for (; e + 8 <= end; e += 8) {
        int s[8];
#pragma unroll
        for (int q = 0; q < 8; q++) s[q] = __ldg(g_srcidx + e + q);
        float4 v[8];
#pragma unroll
        for (int q = 0; q < 8; q++) v[q] = __ldg(f4 + (((size_t)s[q]) << 5) + lane);
#pragma unroll
        for (int q = 0; q < 8; q++) {
            acc.x += v[q].x; acc.y += v[q].y; acc.z += v[q].z; acc.w += v[q].w;
        }
    }
    for (; e < end; e++) {
        int s = __ldg(g_srcidx + e);
        float4 v = __ldg(f4 + (((size_t)s) << 5) + lane);
        acc.x += v.x; acc.y += v.y; acc.z += v.z; acc.w += v.w;
    }
    float inv = 1.0f / fmaxf((float)(end - beg), 1.0f);
    float4 p = __ldg(reinterpret_cast<const float4*>(p1) + (((size_t)w) << 5) + lane);
    float4 b = __ldg(reinterpret_cast<const float4*>(bias) + lane);
    float4 r;
    r.x = fmaxf(fmaf(acc.x, inv, p.x + b.x), 0.f);
    r.y = fmaxf(fmaf(acc.y, inv, p.y + b.y), 0.f);
    r.z = fmaxf(fmaf(acc.z, inv, p.z + b.z), 0.f);
    r.w = fmaxf(fmaf(acc.w, inv, p.w + b.w), 0.f);
    reinterpret_cast<float4*>(h)[(((size_t)w) << 5) + lane] = r;
}

__global__ void gather_add_kernel(const float* __restrict__ t2,
                                  const float* __restrict__ p2,
                                  const float* __restrict__ bias,
                                  float* __restrict__ out, int N) {
    int w = (int)(((size_t)blockIdx.x * blockDim.x + threadIdx.x) >> 5);
    int lane = threadIdx.x & 31;
    if (w >= N) return;
    int beg = __ldg(&g_rowptr[w]);
    int end = __ldg(&g_rowptr[w + 1]);
    float2 acc = make_float2(0.f, 0.f);
    const float2* f2 = reinterpret_cast<const float2*>(t2);
    int e = beg;
    for (; e + 8 <= end; e += 8) {
        int s[8];
#pragma unroll
        for (int q = 0; q < 8; q++) s[q] = __ldg(g_srcidx + e + q);
        float2 v[8];
#pragma unroll
        for (int q = 0; q < 8; q++) v[q] = __ldg(f2 + (((size_t)s[q]) << 5) + lane);
#pragma unroll
        for (int q = 0; q < 8; q++) { acc.x += v[q].x; acc.y += v[q].y; }
    }
    for (; e < end; e++) {
        int s = __ldg(g_srcidx + e);
        float2 v = __ldg(f2 + (((size_t)s) << 5) + lane);
        acc.x += v.x; acc.y += v.y;
    }
    float inv = 1.0f / fmaxf((float)(end - beg), 1.0f);
    float2 p = __ldg(reinterpret_cast<const float2*>(p2) + (((size_t)w) << 5) + lane);
    float2 b = __ldg(reinterpret_cast<const float2*>(bias) + lane);
    float2 r;
    r.x = fmaf(acc.x, inv, p.x + b.x);
    r.y = fmaf(acc.y, inv, p.y + b.y);
    reinterpret_cast<float2*>(out)[(((size_t)w) << 5) + lane] = r;
}

// ---------------------------------------------------------------------------
// kernel_launch: CSR build forked onto a side stream, overlapping gemm1.
// ---------------------------------------------------------------------------
extern "C" void kernel_launch(void* const* d_in, const int* in_sizes, int n_in,
                              void* d_out, int out_size) {
    const float* x   = (const float*)d_in[0];
    const int*   ei  = (const int*)d_in[1];
    const float* W1l = (const float*)d_in[2];
    const float* W1r = (const float*)d_in[3];
    const float* b1  = (const float*)d_in[4];
    const float* W2l = (const float*)d_in[5];
    const float* W2r = (const float*)d_in[6];
    const float* b2  = (const float*)d_in[7];
    float* out = (float*)d_out;

    const int N = in_sizes[0] / 128;
    const int E = in_sizes[1] / 2;
    const int* esrc = ei;
    const int* edst = ei + E;

    void *pp1, *pt1, *ph;
    cudaGetSymbolAddress(&pp1, g_p1);
    cudaGetSymbolAddress(&pt1, g_t1);
    cudaGetSymbolAddress(&ph, g_h);
    float* p1 = (float*)pp1;
    float* t1 = (float*)pt1;
    float* h  = (float*)ph;
    float* p2 = p1;
    float* t2 = t1;

    static cudaStream_t side = nullptr;
    static cudaEvent_t ev_fork = nullptr, ev_join = nullptr;
    static bool attr_set = false;
    if (!side) {
        cudaStreamCreateWithFlags(&side, cudaStreamNonBlocking);
        cudaEventCreateWithFlags(&ev_fork, cudaEventDisableTiming);
        cudaEventCreateWithFlags(&ev_join, cudaEventDisableTiming);
    }
    if (!attr_set) {
        cudaFuncSetAttribute(gemm_tc, cudaFuncAttributeMaxDynamicSharedMemorySize,
                             GEMM_SMEM_BYTES);
        attr_set = true;
    }

    const int wblocks = (N * 32 + 255) / 256;
    const int gx = (N + 127) / 128;

    // Fork: CSR build on side stream, gemm1 on main stream.
    cudaEventRecord(ev_fork, 0);
    cudaStreamWaitEvent(side, ev_fork, 0);
    zero_count_kernel<<<(NODES + 255) / 256, 256, 0, side>>>();
    hist_kernel<<<(E + 255) / 256, 256, 0, side>>>(edst, E);
    scan_kernel<<<1, 1024, 0, side>>>(E);
    fill_kernel<<<(E + 255) / 256, 256, 0, side>>>(esrc, edst, E);
    cudaEventRecord(ev_join, side);

    // Layer 1: [p1|t1] = x @ [W1_r | W1_l]
    gemm_tc<<<dim3(gx, 2), 256, GEMM_SMEM_BYTES>>>(x, W1r, W1l, p1, t1, 128, N);

    // Join: gather needs CSR + gemm1.
    cudaStreamWaitEvent(0, ev_join, 0);
    gather_relu_kernel<<<wblocks, 256>>>(t1, p1, b1, h, N);

    // Layer 2
    gemm_tc<<<dim3(gx, 1), 256, GEMM_SMEM_BYTES>>>(h, W2r, W2l, p2, t2, 64, N);
    gather_add_kernel<<<wblocks, 256>>>(t2, p2, b2, out, N);
}

// round 7
// speedup vs baseline: 1.6652x; 1.1912x over previous
#include <cuda_runtime.h>
#include <cuda_bf16.h>
#include <cstdint>
#include <cstddef>

#define NODES 100000
#define EDGES 1600000

// ---------------------------------------------------------------------------
// Scratch (__device__ globals; no allocation allowed anywhere).
// ---------------------------------------------------------------------------
__device__ float g_p1[(size_t)NODES * 128];   // layer1: x@W1_r ; layer2: p2 (N*64)
__device__ float g_t1[(size_t)NODES * 128];   // layer1: x@W1_l ; layer2: t2 (N*64)
__device__ float g_h[(size_t)NODES * 128];
__device__ int   g_count[NODES];
__device__ int   g_rowptr[NODES + 1];
__device__ int   g_cursor[NODES];
__device__ int   g_srcidx[EDGES];
// Pre-transposed, bf16 hi/lo-split weights: Bt[n][k], n = output col.
__device__ unsigned short g_bt1h[256 * 128];
__device__ unsigned short g_bt1l[256 * 128];
__device__ unsigned short g_bt2h[128 * 128];
__device__ unsigned short g_bt2l[128 * 128];

// ---------------------------------------------------------------------------
// CSR build: zero counts -> histogram -> scan -> fill
// ---------------------------------------------------------------------------
__global__ void zero_count_kernel() {
    int i = blockIdx.x * blockDim.x + threadIdx.x;
    if (i < NODES) g_count[i] = 0;
}

__global__ void hist_kernel(const int* __restrict__ edst, int E) {
    int i = blockIdx.x * blockDim.x + threadIdx.x;
    if (i < E) atomicAdd(&g_count[__ldg(edst + i)], 1);
}

__global__ void scan_kernel(int E) {
    __shared__ int sums[1024];
    const int tid = threadIdx.x;
    const int CH = (NODES + 1023) / 1024;
    const int beg = tid * CH;
    const int end = min(beg + CH, NODES);
    int s = 0;
    for (int i = beg; i < end; i++) s += g_count[i];
    sums[tid] = s;
    __syncthreads();
    for (int off = 1; off < 1024; off <<= 1) {
        int v = (tid >= off) ? sums[tid - off] : 0;
        __syncthreads();
        sums[tid] += v;
        __syncthreads();
    }
    int run = (tid == 0) ? 0 : sums[tid - 1];
    for (int i = beg; i < end; i++) {
        g_rowptr[i] = run;
        g_cursor[i] = run;
        run += g_count[i];
    }
    if (tid == 0) g_rowptr[NODES] = E;
}

__global__ void fill_kernel(const int* __restrict__ esrc,
                            const int* __restrict__ edst, int E) {
    int i = blockIdx.x * blockDim.x + threadIdx.x;
    if (i >= E) return;
    int d = __ldg(edst + i);
    int s = __ldg(esrc + i);
    int pos = atomicAdd(&g_cursor[d], 1);
    g_srcidx[pos] = s;
}

// ---------------------------------------------------------------------------
// Weight prep: transpose to [n][k] and split fp32 -> bf16 hi/lo.
// grid 384 x 128 threads: blocks 0..255 -> [W1r|W1l] col n; 256..383 -> [W2r|W2l].
// ---------------------------------------------------------------------------
__global__ void prep_weights(const float* __restrict__ W1r,
                             const float* __restrict__ W1l,
                             const float* __restrict__ W2r,
                             const float* __restrict__ W2l) {
    int b = blockIdx.x;
    int k = threadIdx.x;
    float v;
    unsigned short *dh, *dl;
    if (b < 256) {
        int n = b;
        const float* W = (n < 128) ? W1r : W1l;
        v = __ldg(W + (size_t)k * 128 + (n & 127));
        dh = g_bt1h + n * 128 + k;
        dl = g_bt1l + n * 128 + k;
    } else {
        int n = b - 256;
        const float* W = (n < 64) ? W2r : W2l;
        v = __ldg(W + (size_t)k * 64 + (n & 63));
        dh = g_bt2h + n * 128 + k;
        dl = g_bt2l + n * 128 + k;
    }
    __nv_bfloat16 hi = __float2bfloat16(v);
    float lo = v - __bfloat162float(hi);
    *dh = __bfloat16_as_ushort(hi);
    *dl = __bfloat16_as_ushort(__float2bfloat16(lo));
}

// ---------------------------------------------------------------------------
// bf16x3 GEMM via mma.sync.m16n8k16 + ldmatrix.
//   C[128 x 128] per CTA = A[128x128 fp32, split to bf16 h/l] @ Bt^T (presplit).
//   Bt is [nt][k] row-major bf16; this CTA uses rows nt = by*128 + n.
//   Output col jg = by*128 + n: jg < bcols -> out0[row*bcols+jg],
//   else out1[row*bcols + jg-bcols].
// Smem rows padded to 136 bf16 (272B): stride 17x16B ≡ 1 mod 8 -> ldmatrix
// 8-row groups conflict-free.
// 8 warps in 4m x 2n grid, warp tile 32x64. 3 passes fused: hh + lh + hl.
// ---------------------------------------------------------------------------
#define LDK 136
#define GEMM_SMEM_BYTES (4 * 128 * LDK * 2)   // Ah, Al, Bh, Bl = 139264

__device__ __forceinline__ uint32_t smem_u32(const void* p) {
    uint32_t a;
    asm("{ .reg .u64 t; cvta.to.shared.u64 t, %1; cvt.u32.u64 %0, t; }"
        : "=r"(a) : "l"(p));
    return a;
}

__device__ __forceinline__ void ldsm_x4(uint32_t r[4], uint32_t addr) {
    asm volatile("ldmatrix.sync.aligned.m8n8.x4.shared.b16 {%0,%1,%2,%3}, [%4];"
                 : "=r"(r[0]), "=r"(r[1]), "=r"(r[2]), "=r"(r[3]) : "r"(addr));
}

__device__ __forceinline__ void mma_bf16(float c[4], const uint32_t a[4],
                                         const uint32_t b0, const uint32_t b1) {
    asm volatile(
        "mma.sync.aligned.m16n8k16.row.col.f32.bf16.bf16.f32 "
        "{%0,%1,%2,%3}, {%4,%5,%6,%7}, {%8,%9}, {%0,%1,%2,%3};"
        : "+f"(c[0]), "+f"(c[1]), "+f"(c[2]), "+f"(c[3])
        : "r"(a[0]), "r"(a[1]), "r"(a[2]), "r"(a[3]), "r"(b0), "r"(b1));
}

__global__ void __launch_bounds__(256, 1) gemm_bf16x3(
    const float* __restrict__ A,
    const unsigned short* __restrict__ Bth,
    const unsigned short* __restrict__ Btl,
    float* __restrict__ out0,
    float* __restrict__ out1,
    int bcols, int Nrows) {
    extern __shared__ __align__(16) char smem[];
    constexpr int AH = 0;
    constexpr int AL = 128 * LDK * 2;
    constexpr int BH = 2 * 128 * LDK * 2;
    constexpr int BL = 3 * 128 * LDK * 2;

    const int tid = threadIdx.x;
    const int row0 = blockIdx.x * 128;
    const int by = blockIdx.y;

    // ---- A tile: load fp32, split to bf16 hi/lo ----
#pragma unroll
    for (int i = 0; i < 16; i++) {
        int l = tid + i * 256;
        int r = l >> 5;
        int k4 = (l & 31) * 4;
        float4 v = make_float4(0.f, 0.f, 0.f, 0.f);
        int gr = row0 + r;
        if (gr < Nrows)
            v = __ldg(reinterpret_cast<const float4*>(A + (size_t)gr * 128 + k4));
        __nv_bfloat16 h0 = __float2bfloat16(v.x), h1 = __float2bfloat16(v.y);
        __nv_bfloat16 h2 = __float2bfloat16(v.z), h3 = __float2bfloat16(v.w);
        uint32_t ph0 = (uint32_t)__bfloat16_as_ushort(h0) |
                       ((uint32_t)__bfloat16_as_ushort(h1) << 16);
        uint32_t ph1 = (uint32_t)__bfloat16_as_ushort(h2) |
                       ((uint32_t)__bfloat16_as_ushort(h3) << 16);
        __nv_bfloat16 q0 = __float2bfloat16(v.x - __bfloat162float(h0));
        __nv_bfloat16 q1 = __float2bfloat16(v.y - __bfloat162float(h1));
        __nv_bfloat16 q2 = __float2bfloat16(v.z - __bfloat162float(h2));
        __nv_bfloat16 q3 = __float2bfloat16(v.w - __bfloat162float(h3));
        uint32_t pl0 = (uint32_t)__bfloat16_as_ushort(q0) |
                       ((uint32_t)__bfloat16_as_ushort(q1) << 16);
        uint32_t pl1 = (uint32_t)__bfloat16_as_ushort(q2) |
                       ((uint32_t)__bfloat16_as_ushort(q3) << 16);
        int off = r * (LDK * 2) + k4 * 2;
        *reinterpret_cast<uint2*>(smem + AH + off) = make_uint2(ph0, ph1);
        *reinterpret_cast<uint2*>(smem + AL + off) = make_uint2(pl0, pl1);
    }
    // ---- B tile: straight copy of pre-split bf16 (rows by*128 + n) ----
#pragma unroll
    for (int i = 0; i < 8; i++) {
        int l = tid + i * 256;
        int n = l >> 4;
        int k8 = (l & 15) * 8;
        int off = n * (LDK * 2) + k8 * 2;
        size_t src = ((size_t)(by * 128 + n)) * 128 + k8;
        uint4 vh = __ldg(reinterpret_cast<const uint4*>(Bth + src));
        uint4 vl = __ldg(reinterpret_cast<const uint4*>(Btl + src));
        *reinterpret_cast<uint4*>(smem + BH + off) = vh;
        *reinterpret_cast<uint4*>(smem + BL + off) = vl;
    }
    __syncthreads();

    const int wid = tid >> 5;
    const int lane = tid & 31;
    const int lane8 = lane & 7;
    const int lt = lane >> 3;           // ldmatrix tile id 0..3
    const int gid = lane >> 2;
    const int tig = lane & 3;
    const int wm = (wid & 3) * 32;      // warp m-base
    const int wn = (wid >> 2) * 64;     // warp n-base

    const uint32_t sb = smem_u32(smem);
    // A frag: row = wm + mt*16 + (lt&1)*8 + lane8, k-byte = (lt>>1)*16
    uint32_t aoff0 = sb + (uint32_t)((wm + (lt & 1) * 8 + lane8) * (LDK * 2) +
                                     (lt >> 1) * 16);
    // B frag (per ng covering ntiles 2ng,2ng+1):
    // row n = wn + ng*16 + (lt>>1)*8 + lane8, k-byte = (lt&1)*16
    uint32_t boff0 = sb + BH + (uint32_t)((wn + (lt >> 1) * 8 + lane8) * (LDK * 2) +
                                          (lt & 1) * 16);

    float acc[2][8][4];
#pragma unroll
    for (int mt = 0; mt < 2; mt++)
#pragma unroll
        for (int nt = 0; nt < 8; nt++)
#pragma unroll
            for (int q = 0; q < 4; q++) acc[mt][nt][q] = 0.f;

#pragma unroll 2
    for (int ks = 0; ks < 8; ks++) {
        const uint32_t kbb = ks * 32;   // 16 bf16 = 32 bytes per kstep
        uint32_t ah[2][4], al[2][4];
#pragma unroll
        for (int mt = 0; mt < 2; mt++) {
            uint32_t a = aoff0 + mt * 16 * (LDK * 2) + kbb;
            ldsm_x4(ah[mt], a + AH);
            ldsm_x4(al[mt], a + AL);
        }
        uint32_t bh[4][4], bl[4][4];
#pragma unroll
        for (int ng = 0; ng < 4; ng++) {
            uint32_t b = boff0 + ng * 16 * (LDK * 2) + kbb;
            ldsm_x4(bh[ng], b);
            ldsm_x4(bl[ng], b + (BL - BH));
        }
#pragma unroll
        for (int mt = 0; mt < 2; mt++)
#pragma unroll
            for (int nt = 0; nt < 8; nt++) {
                const uint32_t* BH2 = bh[nt >> 1];
                const uint32_t* BL2 = bl[nt >> 1];
                uint32_t b0h = BH2[(nt & 1) * 2], b1h = BH2[(nt & 1) * 2 + 1];
                uint32_t b0l = BL2[(nt & 1) * 2], b1l = BL2[(nt & 1) * 2 + 1];
                mma_bf16(acc[mt][nt], ah[mt], b0h, b1h);
                mma_bf16(acc[mt][nt], al[mt], b0h, b1h);
                mma_bf16(acc[mt][nt], ah[mt], b0l, b1l);
            }
    }

    // ---- epilogue ----
#pragma unroll
    for (int mt = 0; mt < 2; mt++) {
#pragma unroll
        for (int nt = 0; nt < 8; nt++) {
            int jg = by * 128 + wn + nt * 8 + 2 * tig;
            int sel = jg >= bcols;
            float* o = sel ? out1 : out0;
            int col = jg - sel * bcols;
            int m0 = row0 + wm + mt * 16 + gid;
            int m1 = m0 + 8;
            if (m0 < Nrows) {
                float2 v = make_float2(acc[mt][nt][0], acc[mt][nt][1]);
                *reinterpret_cast<float2*>(o + (size_t)m0 * bcols + col) = v;
            }
            if (m1 < Nrows) {
                float2 v = make_float2(acc[mt][nt][2], acc[mt][nt][3]);
                *reinterpret_cast<float2*>(o + (size_t)m1 * bcols + col) = v;
            }
        }
    }
}

// ---------------------------------------------------------------------------
// Fused gather epilogues (one warp per node, edge-unrolled by 8).
// Layer1: h = relu(p1 + b1 + mean(t1[src]))       (128-wide, float4/lane)
// Layer2: out = p2 + b2 + mean(t2[src])           (64-wide, float2/lane)
// ---------------------------------------------------------------------------
__global__ void gather_relu_kernel(const float* __restrict__ t1,
                                   const float* __restrict__ p1,
                                   const float* __restrict__ bias,
                                   float* __restrict__ h, int N) {
    int w = (int)(((size_t)blockIdx.x * blockDim.x + threadIdx.x) >> 5);
    int lane = threadIdx.x & 31;
    if (w >= N) return;
    int beg = __ldg(&g_rowptr[w]);
    int end = __ldg(&g_rowptr[w + 1]);
    float4 acc = make_float4(0.f, 0.f, 0.f, 0.f);
    const float4* f4 = reinterpret_cast<const float4*>(t1);
    int e = beg;
    for (; e + 8 <= end; e += 8) {
        int s[8];
#pragma unroll
        for (int q = 0; q < 8; q++) s[q] = __ldg(g_srcidx + e + q);
        float4 v[8];
#pragma unroll
        for (int q = 0; q < 8; q++) v[q] = __ldg(f4 + (((size_t)s[q]) << 5) + lane);
#pragma unroll
        for (int q = 0; q < 8; q++) {
            acc.x += v[q].x; acc.y += v[q].y; acc.z += v[q].z; acc.w += v[q].w;
        }
    }
    for (; e < end; e++) {
        int s = __ldg(g_srcidx + e);
        float4 v = __ldg(f4 + (((size_t)s) << 5) + lane);
        acc.x += v.x; acc.y += v.y; acc.z += v.z; acc.w += v.w;
    }
    float inv = 1.0f / fmaxf((float)(end - beg), 1.0f);
    float4 p = __ldg(reinterpret_cast<const float4*>(p1) + (((size_t)w) << 5) + lane);
    float4 b = __ldg(reinterpret_cast<const float4*>(bias) + lane);
    float4 r;
    r.x = fmaxf(fmaf(acc.x, inv, p.x + b.x), 0.f);
    r.y = fmaxf(fmaf(acc.y, inv, p.y + b.y), 0.f);
    r.z = fmaxf(fmaf(acc.z, inv, p.z + b.z), 0.f);
    r.w = fmaxf(fmaf(acc.w, inv, p.w + b.w), 0.f);
    reinterpret_cast<float4*>(h)[(((size_t)w) << 5) + lane] = r;
}

__global__ void gather_add_kernel(const float* __restrict__ t2,
                                  const float* __restrict__ p2,
                                  const float* __restrict__ bias,
                                  float* __restrict__ out, int N) {
    int w = (int)(((size_t)blockIdx.x * blockDim.x + threadIdx.x) >> 5);
    int lane = threadIdx.x & 31;
    if (w >= N) return;
    int beg = __ldg(&g_rowptr[w]);
    int end = __ldg(&g_rowptr[w + 1]);
    float2 acc = make_float2(0.f, 0.f);
    const float2* f2 = reinterpret_cast<const float2*>(t2);
    int e = beg;
    for (; e + 8 <= end; e += 8) {
        int s[8];
#pragma unroll
        for (int q = 0; q < 8; q++) s[q] = __ldg(g_srcidx + e + q);
        float2 v[8];
#pragma unroll
        for (int q = 0; q < 8; q++) v[q] = __ldg(f2 + (((size_t)s[q]) << 5) + lane);
#pragma unroll
        for (int q = 0; q < 8; q++) { acc.x += v[q].x; acc.y += v[q].y; }
    }
    for (; e < end; e++) {
        int s = __ldg(g_srcidx + e);
        float2 v = __ldg(f2 + (((size_t)s) << 5) + lane);
        acc.x += v.x; acc.y += v.y;
    }
    float inv = 1.0f / fmaxf((float)(end - beg), 1.0f);
    float2 p = __ldg(reinterpret_cast<const float2*>(p2) + (((size_t)w) << 5) + lane);
    float2 b = __ldg(reinterpret_cast<const float2*>(bias) + lane);
    float2 r;
    r.x = fmaf(acc.x, inv, p.x + b.x);
    r.y = fmaf(acc.y, inv, p.y + b.y);
    reinterpret_cast<float2*>(out)[(((size_t)w) << 5) + lane] = r;
}

// ---------------------------------------------------------------------------
// kernel_launch: CSR build forked onto a side stream, overlapping gemm1.
// ---------------------------------------------------------------------------
extern "C" void kernel_launch(void* const* d_in, const int* in_sizes, int n_in,
                              void* d_out, int out_size) {
    const float* x   = (const float*)d_in[0];
    const int*   ei  = (const int*)d_in[1];
    const float* W1l = (const float*)d_in[2];
    const float* W1r = (const float*)d_in[3];
    const float* b1  = (const float*)d_in[4];
    const float* W2l = (const float*)d_in[5];
    const float* W2r = (const float*)d_in[6];
    const float* b2  = (const float*)d_in[7];
    float* out = (float*)d_out;

    const int N = in_sizes[0] / 128;
    const int E = in_sizes[1] / 2;
    const int* esrc = ei;
    const int* edst = ei + E;

    void *pp1, *pt1, *ph, *b1h, *b1l, *b2h, *b2l;
    cudaGetSymbolAddress(&pp1, g_p1);
    cudaGetSymbolAddress(&pt1, g_t1);
    cudaGetSymbolAddress(&ph, g_h);
    cudaGetSymbolAddress(&b1h, g_bt1h);
    cudaGetSymbolAddress(&b1l, g_bt1l);
    cudaGetSymbolAddress(&b2h, g_bt2h);
    cudaGetSymbolAddress(&b2l, g_bt2l);
    float* p1 = (float*)pp1;
    float* t1 = (float*)pt1;
    float* h  = (float*)ph;
    float* p2 = p1;
    float* t2 = t1;

    static cudaStream_t side = nullptr;
    static cudaEvent_t ev_fork = nullptr, ev_join = nullptr;
    static bool attr_set = false;
    if (!side) {
        cudaStreamCreateWithFlags(&side, cudaStreamNonBlocking);
        cudaEventCreateWithFlags(&ev_fork, cudaEventDisableTiming);
        cudaEventCreateWithFlags(&ev_join, cudaEventDisableTiming);
    }
    if (!attr_set) {
        cudaFuncSetAttribute(gemm_bf16x3,
                             cudaFuncAttributeMaxDynamicSharedMemorySize,
                             GEMM_SMEM_BYTES);
        attr_set = true;
    }

    const int wblocks = (N * 32 + 255) / 256;
    const int gx = (N + 127) / 128;

    // Fork: CSR build on side stream.
    cudaEventRecord(ev_fork, 0);
    cudaStreamWaitEvent(side, ev_fork, 0);
    zero_count_kernel<<<(NODES + 255) / 256, 256, 0, side>>>();
    hist_kernel<<<(E + 255) / 256, 256, 0, side>>>(edst, E);
    scan_kernel<<<1, 1024, 0, side>>>(E);
    fill_kernel<<<(E + 255) / 256, 256, 0, side>>>(esrc, edst, E);
    cudaEventRecord(ev_join, side);

    // Weight prep (main stream; gemm1 depends on it).
    prep_weights<<<384, 128>>>(W1r, W1l, W2r, W2l);

    // Layer 1: [p1 | t1] = x @ [W1_r | W1_l]
    // grid.y=2: by=0 -> Bt rows 0..127 -> cols 0..127 -> p1;
    //           by=1 -> Bt rows 128..255 -> cols 128..255 -> t1.
    gemm_bf16x3<<<dim3(gx, 2), 256, GEMM_SMEM_BYTES>>>(
        x, (const unsigned short*)b1h, (const unsigned short*)b1l,
        p1, t1, 128, N);

    cudaStreamWaitEvent(0, ev_join, 0);
    gather_relu_kernel<<<wblocks, 256>>>(t1, p1, b1, h, N);

    // Layer 2: [p2 | t2] = h @ [W2_r | W2_l]  (128 Bt rows total, by=0 only)
    gemm_bf16x3<<<dim3(gx, 1), 256, GEMM_SMEM_BYTES>>>(
        h, (const unsigned short*)b2h, (const unsigned short*)b2l,
        p2, t2, 64, N);
    gather_add_kernel<<<wblocks, 256>>>(t2, p2, b2, out, N);
}

// round 9
// speedup vs baseline: 1.7380x; 1.0437x over previous
#include <cuda_runtime.h>
#include <cuda_fp16.h>
#include <cstdint>
#include <cstddef>

#define NODES 100000
#define EDGES 1600000

// ---------------------------------------------------------------------------
// Scratch (__device__ globals; no allocation allowed anywhere).
// ---------------------------------------------------------------------------
__device__ float g_p1[(size_t)NODES * 128];   // layer1: x@W1_r
__device__ float g_t1[(size_t)NODES * 128];   // layer1: x@W1_l
__device__ float g_h[(size_t)NODES * 128];    // fp16 hi/lo planes of h
__device__ float g_o[(size_t)NODES * 128];    // layer2: p2 (N*64) | t2 (N*64)
__device__ int   g_count[NODES];
__device__ int   g_rowptr[NODES + 1];
__device__ int   g_cursor[NODES];
__device__ int   g_srcidx[EDGES];
// Pre-transposed fp16 weights (hi only): Bt[n][k], n = output col.
__device__ unsigned short g_bt1h[256 * 128];
__device__ unsigned short g_bt2h[128 * 128];

// ---------------------------------------------------------------------------
// CSR build: zero counts -> histogram -> scan -> fill
// ---------------------------------------------------------------------------
__global__ void zero_count_kernel() {
    int i = blockIdx.x * blockDim.x + threadIdx.x;
    if (i < NODES) g_count[i] = 0;
}

__global__ void hist_kernel(const int* __restrict__ edst, int E) {
    int i = blockIdx.x * blockDim.x + threadIdx.x;
    if (i < E) atomicAdd(&g_count[__ldg(edst + i)], 1);
}

__global__ void scan_kernel(int E) {
    __shared__ int sums[1024];
    const int tid = threadIdx.x;
    const int CH = (NODES + 1023) / 1024;
    const int beg = tid * CH;
    const int end = min(beg + CH, NODES);
    int s = 0;
    for (int i = beg; i < end; i++) s += g_count[i];
    sums[tid] = s;
    __syncthreads();
    for (int off = 1; off < 1024; off <<= 1) {
        int v = (tid >= off) ? sums[tid - off] : 0;
        __syncthreads();
        sums[tid] += v;
        __syncthreads();
    }
    int run = (tid == 0) ? 0 : sums[tid - 1];
    for (int i = beg; i < end; i++) {
        g_rowptr[i] = run;
        g_cursor[i] = run;
        run += g_count[i];
    }
    if (tid == 0) g_rowptr[NODES] = E;
}

__global__ void fill_kernel(const int* __restrict__ esrc,
                            const int* __restrict__ edst, int E) {
    int i = blockIdx.x * blockDim.x + threadIdx.x;
    if (i >= E) return;
    int d = __ldg(edst + i);
    int s = __ldg(esrc + i);
    int pos = atomicAdd(&g_cursor[d], 1);
    g_srcidx[pos] = s;
}

// ---------------------------------------------------------------------------
// Weight prep: transpose to [n][k], fp16 (hi only).
// ---------------------------------------------------------------------------
__global__ void prep_weights(const float* __restrict__ W1r,
                             const float* __restrict__ W1l,
                             const float* __restrict__ W2r,
                             const float* __restrict__ W2l) {
    int b = blockIdx.x;
    int k = threadIdx.x;
    float v;
    unsigned short* dh;
    if (b < 256) {
        int n = b;
        const float* W = (n < 128) ? W1r : W1l;
        v = __ldg(W + (size_t)k * 128 + (n & 127));
        dh = g_bt1h + n * 128 + k;
    } else {
        int n = b - 256;
        const float* W = (n < 64) ? W2r : W2l;
        v = __ldg(W + (size_t)k * 64 + (n & 63));
        dh = g_bt2h + n * 128 + k;
    }
    *dh = __half_as_ushort(__float2half_rn(v));
}

// ---------------------------------------------------------------------------
// fp16x2 GEMM helpers (mma.sync.m16n8k16.f16 + ldmatrix).
// ---------------------------------------------------------------------------
#define LDKB 272   // smem bytes per 128-col fp16 row (136 * 2)

__device__ __forceinline__ uint32_t smem_u32(const void* p) {
    uint32_t a;
    asm("{ .reg .u64 t; cvta.to.shared.u64 t, %1; cvt.u32.u64 %0, t; }"
        : "=r"(a) : "l"(p));
    return a;
}

__device__ __forceinline__ void ldsm_x4(uint32_t r[4], uint32_t addr) {
    asm volatile("ldmatrix.sync.aligned.m8n8.x4.shared.b16 {%0,%1,%2,%3}, [%4];"
                 : "=r"(r[0]), "=r"(r[1]), "=r"(r[2]), "=r"(r[3]) : "r"(addr));
}

__device__ __forceinline__ void mma_f16(float c[4], const uint32_t a[4],
                                        const uint32_t b0, const uint32_t b1) {
    asm volatile(
        "mma.sync.aligned.m16n8k16.row.col.f32.f16.f16.f32 "
        "{%0,%1,%2,%3}, {%4,%5,%6,%7}, {%8,%9}, {%0,%1,%2,%3};"
        : "+f"(c[0]), "+f"(c[1]), "+f"(c[2]), "+f"(c[3])
        : "r"(a[0]), "r"(a[1]), "r"(a[2]), "r"(a[3]), "r"(b0), "r"(b1));
}

// ---------------------------------------------------------------------------
// gemm1: C[128 x 256] per CTA = A[128x128 fp32 -> fp16 h/l] @ Bt1^T (fp16).
// jg < bcols -> out0[row*bcols+jg], else out1[row*bcols + jg-bcols].
// 8 warps 4m x 2n, warp tile 32x128. 2 passes: ah*bh + al*bh.
// ---------------------------------------------------------------------------
#define SMEM1 (2 * 128 * LDKB + 256 * LDKB)   // Ah, Al, Bh(256 rows) = 139264

__global__ void __launch_bounds__(256, 1) gemm1_tc(
    const float* __restrict__ A,
    const unsigned short* __restrict__ Bth,
    float* __restrict__ out0,
    float* __restrict__ out1,
    int bcols, int Nrows) {
    extern __shared__ __align__(16) char smem[];
    constexpr int AH = 0;
    constexpr int AL = 128 * LDKB;
    constexpr int BH = 2 * 128 * LDKB;

    const int tid = threadIdx.x;
    const int row0 = blockIdx.x * 128;

    // ---- A tile: load fp32, split to fp16 hi/lo ----
#pragma unroll
    for (int i = 0; i < 16; i++) {
        int l = tid + i * 256;
        int r = l >> 5;
        int k4 = (l & 31) * 4;
        float4 v = make_float4(0.f, 0.f, 0.f, 0.f);
        int gr = row0 + r;
        if (gr < Nrows)
            v = __ldg(reinterpret_cast<const float4*>(A + (size_t)gr * 128 + k4));
        __half h0 = __float2half_rn(v.x), h1 = __float2half_rn(v.y);
        __half h2 = __float2half_rn(v.z), h3 = __float2half_rn(v.w);
        uint32_t ph0 = (uint32_t)__half_as_ushort(h0) |
                       ((uint32_t)__half_as_ushort(h1) << 16);
        uint32_t ph1 = (uint32_t)__half_as_ushort(h2) |
                       ((uint32_t)__half_as_ushort(h3) << 16);
        __half q0 = __float2half_rn(v.x - __half2float(h0));
        __half q1 = __float2half_rn(v.y - __half2float(h1));
        __half q2 = __float2half_rn(v.z - __half2float(h2));
        __half q3 = __float2half_rn(v.w - __half2float(h3));
        uint32_t pl0 = (uint32_t)__half_as_ushort(q0) |
                       ((uint32_t)__half_as_ushort(q1) << 16);
        uint32_t pl1 = (uint32_t)__half_as_ushort(q2) |
                       ((uint32_t)__half_as_ushort(q3) << 16);
        int off = r * LDKB + k4 * 2;
        *reinterpret_cast<uint2*>(smem + AH + off) = make_uint2(ph0, ph1);
        *reinterpret_cast<uint2*>(smem + AL + off) = make_uint2(pl0, pl1);
    }
    // ---- B tile: copy 256 fp16 rows ----
#pragma unroll
    for (int i = 0; i < 16; i++) {
        int l = tid + i * 256;
        int n = l >> 4;
        int k8 = (l & 15) * 8;
        uint4 vh = __ldg(reinterpret_cast<const uint4*>(Bth + (size_t)n * 128 + k8));
        *reinterpret_cast<uint4*>(smem + BH + n * LDKB + k8 * 2) = vh;
    }
    __syncthreads();

    const int wid = tid >> 5;
    const int lane = tid & 31;
    const int lane8 = lane & 7;
    const int lt = lane >> 3;
    const int gid = lane >> 2;
    const int tig = lane & 3;
    const int wm = (wid & 3) * 32;
    const int wn = (wid >> 2) * 128;

    const uint32_t sb = smem_u32(smem);
    uint32_t aoff0 = sb + (uint32_t)((wm + (lt & 1) * 8 + lane8) * LDKB +
                                     (lt >> 1) * 16);
    uint32_t boff0 = sb + BH + (uint32_t)((wn + (lt >> 1) * 8 + lane8) * LDKB +
                                          (lt & 1) * 16);

    float acc[2][16][4];
#pragma unroll
    for (int mt = 0; mt < 2; mt++)
#pragma unroll
        for (int nt = 0; nt < 16; nt++)
#pragma unroll
            for (int q = 0; q < 4; q++) acc[mt][nt][q] = 0.f;

#pragma unroll 1
    for (int ks = 0; ks < 8; ks++) {
        const uint32_t kbb = ks * 32;
        uint32_t ah[2][4], al[2][4];
#pragma unroll
        for (int mt = 0; mt < 2; mt++) {
            uint32_t a = aoff0 + mt * 16 * LDKB + kbb;
            ldsm_x4(ah[mt], a);
            ldsm_x4(al[mt], a + (AL - AH));
        }
#pragma unroll
        for (int ng = 0; ng < 8; ng++) {
            uint32_t bb[4];
            ldsm_x4(bb, boff0 + ng * 16 * LDKB + kbb);
#pragma unroll
            for (int mt = 0; mt < 2; mt++)
#pragma unroll
                for (int s = 0; s < 2; s++) {
                    int nt = ng * 2 + s;
                    mma_f16(acc[mt][nt], ah[mt], bb[s * 2], bb[s * 2 + 1]);
                    mma_f16(acc[mt][nt], al[mt], bb[s * 2], bb[s * 2 + 1]);
                }
        }
    }

    // ---- epilogue ----
#pragma unroll
    for (int mt = 0; mt < 2; mt++) {
#pragma unroll
        for (int nt = 0; nt < 16; nt++) {
            int jg = wn + nt * 8 + 2 * tig;
            int sel = jg >= bcols;
            float* o = sel ? out1 : out0;
            int col = jg - sel * bcols;
            int m0 = row0 + wm + mt * 16 + gid;
            int m1 = m0 + 8;
            if (m0 < Nrows) {
                float2 v = make_float2(acc[mt][nt][0], acc[mt][nt][1]);
                *reinterpret_cast<float2*>(o + (size_t)m0 * bcols + col) = v;
            }
            if (m1 < Nrows) {
                float2 v = make_float2(acc[mt][nt][2], acc[mt][nt][3]);
                *reinterpret_cast<float2*>(o + (size_t)m1 * bcols + col) = v;
            }
        }
    }
}

// ---------------------------------------------------------------------------
// gemm2: C[128 x 128] per CTA = H(presplit fp16 h/l planes) @ Bt2^T (fp16).
// ---------------------------------------------------------------------------
#define SMEM2 (3 * 128 * LDKB)   // Ah, Al, Bh = 104448

__global__ void __launch_bounds__(256, 1) gemm2_tc(
    const unsigned short* __restrict__ Ahh,
    const unsigned short* __restrict__ Ahl,
    const unsigned short* __restrict__ Bth,
    float* __restrict__ out0,
    float* __restrict__ out1,
    int bcols, int Nrows) {
    extern __shared__ __align__(16) char smem[];
    constexpr int AH = 0;
    constexpr int AL = 128 * LDKB;
    constexpr int BH = 2 * 128 * LDKB;

    const int tid = threadIdx.x;
    const int row0 = blockIdx.x * 128;

    // ---- A tile: copy pre-split fp16 planes ----
#pragma unroll
    for (int i = 0; i < 8; i++) {
        int l = tid + i * 256;
        int r = l >> 4;
        int k8 = (l & 15) * 8;
        uint4 vh = make_uint4(0, 0, 0, 0), vl = make_uint4(0, 0, 0, 0);
        int gr = row0 + r;
        if (gr < Nrows) {
            size_t src = (size_t)gr * 128 + k8;
            vh = __ldg(reinterpret_cast<const uint4*>(Ahh + src));
            vl = __ldg(reinterpret_cast<const uint4*>(Ahl + src));
        }
        int off = r * LDKB + k8 * 2;
        *reinterpret_cast<uint4*>(smem + AH + off) = vh;
        *reinterpret_cast<uint4*>(smem + AL + off) = vl;
    }
    // ---- B tile: copy 128 fp16 rows ----
#pragma unroll
    for (int i = 0; i < 8; i++) {
        int l = tid + i * 256;
        int n = l >> 4;
        int k8 = (l & 15) * 8;
        uint4 vh = __ldg(reinterpret_cast<const uint4*>(Bth + (size_t)n * 128 + k8));
        *reinterpret_cast<uint4*>(smem + BH + n * LDKB + k8 * 2) = vh;
    }
    __syncthreads();

    const int wid = tid >> 5;
    const int lane = tid & 31;
    const int lane8 = lane & 7;
    const int lt = lane >> 3;
    const int gid = lane >> 2;
    const int tig = lane & 3;
    const int wm = (wid & 3) * 32;
    const int wn = (wid >> 2) * 64;

    const uint32_t sb = smem_u32(smem);
    uint32_t aoff0 = sb + (uint32_t)((wm + (lt & 1) * 8 + lane8) * LDKB +
                                     (lt >> 1) * 16);
    uint32_t boff0 = sb + BH + (uint32_t)((wn + (lt >> 1) * 8 + lane8) * LDKB +
                                          (lt & 1) * 16);

    float acc[2][8][4];
#pragma unroll
    for (int mt = 0; mt < 2; mt++)
#pragma unroll
        for (int nt = 0; nt < 8; nt++)
#pragma unroll
            for (int q = 0; q < 4; q++) acc[mt][nt][q] = 0.f;

#pragma unroll 2
    for (int ks = 0; ks < 8; ks++) {
        const uint32_t kbb = ks * 32;
        uint32_t ah[2][4], al[2][4];
#pragma unroll
        for (int mt = 0; mt < 2; mt++) {
            uint32_t a = aoff0 + mt * 16 * LDKB + kbb;
            ldsm_x4(ah[mt], a);
            ldsm_x4(al[mt], a + (AL - AH));
        }
#pragma unroll
        for (int ng = 0; ng < 4; ng++) {
            uint32_t bb[4];
            ldsm_x4(bb, boff0 + ng * 16 * LDKB + kbb);
#pragma unroll
            for (int mt = 0; mt < 2; mt++)
#pragma unroll
                for (int s = 0; s < 2; s++) {
                    int nt = ng * 2 + s;
                    mma_f16(acc[mt][nt], ah[mt], bb[s * 2], bb[s * 2 + 1]);
                    mma_f16(acc[mt][nt], al[mt], bb[s * 2], bb[s * 2 + 1]);
                }
        }
    }

#pragma unroll
    for (int mt = 0; mt < 2; mt++) {
#pragma unroll
        for (int nt = 0; nt < 8; nt++) {
            int jg = wn + nt * 8 + 2 * tig;
            int sel = jg >= bcols;
            float* o = sel ? out1 : out0;
            int col = jg - sel * bcols;
            int m0 = row0 + wm + mt * 16 + gid;
            int m1 = m0 + 8;
            if (m0 < Nrows) {
                float2 v = make_float2(acc[mt][nt][0], acc[mt][nt][1]);
                *reinterpret_cast<float2*>(o + (size_t)m0 * bcols + col) = v;
            }
            if (m1 < Nrows) {
                float2 v = make_float2(acc[mt][nt][2], acc[mt][nt][3]);
                *reinterpret_cast<float2*>(o + (size_t)m1 * bcols + col) = v;
            }
        }
    }
}

// ---------------------------------------------------------------------------
// gather_relu: h = relu(p1 + b1 + mean(t1[src])) -> fp16 hi/lo planes.
// One warp per node in [base, limit), edge-unrolled by 8, float4/lane.
// ---------------------------------------------------------------------------
__global__ void gather_relu_kernel(const float* __restrict__ t1,
                                   const float* __restrict__ p1,
                                   const float* __restrict__ bias,
                                   unsigned short* __restrict__ hh,
                                   unsigned short* __restrict__ hl,
                                   int base, int limit) {
    int w = base + (int)(((size_t)blockIdx.x * blockDim.x + threadIdx.x) >> 5);
    int lane = threadIdx.x & 31;
    if (w >= limit) return;
    int beg = __ldg(&g_rowptr[w]);
    int end = __ldg(&g_rowptr[w + 1]);
    float4 acc = make_float4(0.f, 0.f, 0.f, 0.f);
    const float4* f4 = reinterpret_cast<const float4*>(t1);
    int e = beg;
    for (; e + 8 <= end; e += 8) {
        int s[8];
#pragma unroll
        for (int q = 0; q < 8; q++) s[q] = __ldg(g_srcidx + e + q);
        float4 v[8];
#pragma unroll
        for (int q = 0; q < 8; q++) v[q] = __ldg(f4 + (((size_t)s[q]) << 5) + lane);
#pragma unroll
        for (int q = 0; q < 8; q++) {
            acc.x += v[q].x; acc.y += v[q].y; acc.z += v[q].z; acc.w += v[q].w;
        }
    }
    for (; e < end; e++) {
        int s = __ldg(g_srcidx + e);
        float4 v = __ldg(f4 + (((size_t)s) << 5) + lane);
        acc.x += v.x; acc.y += v.y; acc.z += v.z; acc.w += v.w;
    }
    float inv = 1.0f / fmaxf((float)(end - beg), 1.0f);
    float4 p = __ldg(reinterpret_cast<const float4*>(p1) + (((size_t)w) << 5) + lane);
    float4 b = __ldg(reinterpret_cast<const float4*>(bias) + lane);
    float rx = fmaxf(fmaf(acc.x, inv, p.x + b.x), 0.f);
    float ry = fmaxf(fmaf(acc.y, inv, p.y + b.y), 0.f);
    float rz = fmaxf(fmaf(acc.z, inv, p.z + b.z), 0.f);
    float rw = fmaxf(fmaf(acc.w, inv, p.w + b.w), 0.f);
    __half h0 = __float2half_rn(rx), h1 = __float2half_rn(ry);
    __half h2 = __float2half_rn(rz), h3 = __float2half_rn(rw);
    uint32_t ph0 = (uint32_t)__half_as_ushort(h0) |
                   ((uint32_t)__half_as_ushort(h1) << 16);
    uint32_t ph1 = (uint32_t)__half_as_ushort(h2) |
                   ((uint32_t)__half_as_ushort(h3) << 16);
    __half q0 = __float2half_rn(rx - __half2float(h0));
    __half q1 = __float2half_rn(ry - __half2float(h1));
    __half q2 = __float2half_rn(rz - __half2float(h2));
    __half q3 = __float2half_rn(rw - __half2float(h3));
    uint32_t pl0 = (uint32_t)__half_as_ushort(q0) |
                   ((uint32_t)__half_as_ushort(q1) << 16);
    uint32_t pl1 = (uint32_t)__half_as_ushort(q2) |
                   ((uint32_t)__half_as_ushort(q3) << 16);
    size_t ofs = (size_t)w * 128 + lane * 4;
    *reinterpret_cast<uint2*>(hh + ofs) = make_uint2(ph0, ph1);
    *reinterpret_cast<uint2*>(hl + ofs) = make_uint2(pl0, pl1);
}

// ---------------------------------------------------------------------------
// gather_add: out = p2 + b2 + mean(t2[src])   (64-wide, float2/lane)
// ---------------------------------------------------------------------------
__global__ void gather_add_kernel(const float* __restrict__ t2,
                                  const float* __restrict__ p2,
                                  const float* __restrict__ bias,
                                  float* __restrict__ out, int N) {
    int w = (int)(((size_t)blockIdx.x * blockDim.x + threadIdx.x) >> 5);
    int lane = threadIdx.x & 31;
    if (w >= N) return;
    int beg = __ldg(&g_rowptr[w]);
    int end = __ldg(&g_rowptr[w + 1]);
    float2 acc = make_float2(0.f, 0.f);
    const float2* f2 = reinterpret_cast<const float2*>(t2);
    int e = beg;
    for (; e + 8 <= end; e += 8) {
        int s[8];
#pragma unroll
        for (int q = 0; q < 8; q++) s[q] = __ldg(g_srcidx + e + q);
        float2 v[8];
#pragma unroll
        for (int q = 0; q < 8; q++) v[q] = __ldg(f2 + (((size_t)s[q]) << 5) + lane);
#pragma unroll
        for (int q = 0; q < 8; q++) { acc.x += v[q].x; acc.y += v[q].y; }
    }
    for (; e < end; e++) {
        int s = __ldg(g_srcidx + e);
        float2 v = __ldg(f2 + (((size_t)s) << 5) + lane);
        acc.x += v.x; acc.y += v.y;
    }
    float inv = 1.0f / fmaxf((float)(end - beg), 1.0f);
    float2 p = __ldg(reinterpret_cast<const float2*>(p2) + (((size_t)w) << 5) + lane);
    float2 b = __ldg(reinterpret_cast<const float2*>(bias) + lane);
    float2 r;
    r.x = fmaf(acc.x, inv, p.x + b.x);
    r.y = fmaf(acc.y, inv, p.y + b.y);
    reinterpret_cast<float2*>(out)[(((size_t)w) << 5) + lane] = r;
}

// ---------------------------------------------------------------------------
// kernel_launch: CSR on side stream; gather_relu chunks pipelined with gemm2.
// p2/t2 live in g_o (NO aliasing with t1/p1 — the R8 race).
// ---------------------------------------------------------------------------
extern "C" void kernel_launch(void* const* d_in, const int* in_sizes, int n_in,
                              void* d_out, int out_size) {
    const float* x   = (const float*)d_in[0];
    const int*   ei  = (const int*)d_in[1];
    const float* W1l = (const float*)d_in[2];
    const float* W1r = (const float*)d_in[3];
    const float* b1  = (const float*)d_in[4];
    const float* W2l = (const float*)d_in[5];
    const float* W2r = (const float*)d_in[6];
    const float* b2  = (const float*)d_in[7];
    float* out = (float*)d_out;

    const int N = in_sizes[0] / 128;
    const int E = in_sizes[1] / 2;
    const int* esrc = ei;
    const int* edst = ei + E;

    void *pp1, *pt1, *ph, *po, *b1h, *b2h;
    cudaGetSymbolAddress(&pp1, g_p1);
    cudaGetSymbolAddress(&pt1, g_t1);
    cudaGetSymbolAddress(&ph, g_h);
    cudaGetSymbolAddress(&po, g_o);
    cudaGetSymbolAddress(&b1h, g_bt1h);
    cudaGetSymbolAddress(&b2h, g_bt2h);
    float* p1 = (float*)pp1;
    float* t1 = (float*)pt1;
    float* p2 = (float*)po;                                // [N][64]
    float* t2 = (float*)po + (size_t)NODES * 64;           // [N][64]
    unsigned short* hh = (unsigned short*)ph;              // [N][128] fp16 hi
    unsigned short* hl = hh + (size_t)NODES * 128;         // [N][128] fp16 lo
    const unsigned short* bt1h = (const unsigned short*)b1h;
    const unsigned short* bt2h = (const unsigned short*)b2h;

    static cudaStream_t side = nullptr;
    static cudaEvent_t ev_fork = nullptr, ev_join = nullptr, ev_g2 = nullptr;
    static cudaEvent_t ev_gr[4] = {nullptr, nullptr, nullptr, nullptr};
    static bool attr_set = false;
    if (!side) {
        cudaStreamCreateWithFlags(&side, cudaStreamNonBlocking);
        cudaEventCreateWithFlags(&ev_fork, cudaEventDisableTiming);
        cudaEventCreateWithFlags(&ev_join, cudaEventDisableTiming);
        cudaEventCreateWithFlags(&ev_g2, cudaEventDisableTiming);
        for (int c = 0; c < 4; c++)
            cudaEventCreateWithFlags(&ev_gr[c], cudaEventDisableTiming);
    }
    if (!attr_set) {
        cudaFuncSetAttribute(gemm1_tc,
                             cudaFuncAttributeMaxDynamicSharedMemorySize, SMEM1);
        cudaFuncSetAttribute(gemm2_tc,
                             cudaFuncAttributeMaxDynamicSharedMemorySize, SMEM2);
        attr_set = true;
    }

    const int gx = (N + 127) / 128;

    // Fork: CSR build on side stream.
    cudaEventRecord(ev_fork, 0);
    cudaStreamWaitEvent(side, ev_fork, 0);
    zero_count_kernel<<<(NODES + 255) / 256, 256, 0, side>>>();
    hist_kernel<<<(E + 255) / 256, 256, 0, side>>>(edst, E);
    scan_kernel<<<1, 1024, 0, side>>>(E);
    fill_kernel<<<(E + 255) / 256, 256, 0, side>>>(esrc, edst, E);
    cudaEventRecord(ev_join, side);

    // Weight prep + layer-1 GEMM (main stream).
    prep_weights<<<384, 128>>>(W1r, W1l, W2r, W2l);
    gemm1_tc<<<gx, 256, SMEM1>>>(x, bt1h, p1, t1, 128, N);

    // gather_relu needs CSR.
    cudaStreamWaitEvent(0, ev_join, 0);

    // Pipelined: gather_relu chunk c (main)  ->  gemm2 chunk c (side).
    const int tpc = (gx + 3) / 4;
    for (int c = 0; c < 4; c++) {
        int t0 = c * tpc;
        if (t0 >= gx) { cudaEventRecord(ev_gr[c], 0); continue; }
        int tc = (gx - t0 < tpc) ? (gx - t0) : tpc;
        int r0 = t0 * 128;
        int rc = (N - r0 < tc * 128) ? (N - r0) : tc * 128;
        int wb = (rc * 32 + 255) / 256;
        gather_relu_kernel<<<wb, 256>>>(t1, p1, b1, hh, hl, r0, r0 + rc);
        cudaEventRecord(ev_gr[c], 0);
        cudaStreamWaitEvent(side, ev_gr[c], 0);
        gemm2_tc<<<tc, 256, SMEM2, side>>>(
            hh + (size_t)r0 * 128, hl + (size_t)r0 * 128, bt2h,
            p2 + (size_t)r0 * 64, t2 + (size_t)r0 * 64, 64, rc);
    }
    cudaEventRecord(ev_g2, side);
    cudaStreamWaitEvent(0, ev_g2, 0);

    const int wblocks = (N * 32 + 255) / 256;
    gather_add_kernel<<<wblocks, 256>>>(t2, p2, b2, out, N);
}

// round 10
// speedup vs baseline: 1.8910x; 1.0881x over previous
#include <cuda_runtime.h>
#include <cuda_fp16.h>
#include <cstdint>
#include <cstddef>

#define NODES 100000
#define EDGES 1600000

// ---------------------------------------------------------------------------
// Scratch (__device__ globals; no allocation allowed anywhere).
// ---------------------------------------------------------------------------
__device__ float g_p1[(size_t)NODES * 128];            // layer1: x@W1_r (fp32)
__device__ unsigned short g_t1[(size_t)NODES * 128];   // layer1: x@W1_l (fp16)
__device__ float g_h[(size_t)NODES * 128];             // fp16 hi/lo planes of h
__device__ float g_p2[(size_t)NODES * 64];             // layer2: h@W2_r (fp32)
__device__ unsigned short g_t2[(size_t)NODES * 64];    // layer2: h@W2_l (fp16)
__device__ int   g_count[NODES];
__device__ int   g_rowptr[NODES + 1];
__device__ int   g_cursor[NODES];
__device__ int   g_srcidx[EDGES];
// Pre-transposed fp16 weights: Bt[n][k], n = output col.
__device__ unsigned short g_bt1h[256 * 128];
__device__ unsigned short g_bt2h[128 * 128];

// ---------------------------------------------------------------------------
// CSR build: zero counts -> histogram -> scan -> fill
// ---------------------------------------------------------------------------
__global__ void zero_count_kernel() {
    int i = blockIdx.x * blockDim.x + threadIdx.x;
    if (i < NODES) g_count[i] = 0;
}

__global__ void hist_kernel(const int* __restrict__ edst, int E) {
    int i = blockIdx.x * blockDim.x + threadIdx.x;
    if (i < E) atomicAdd(&g_count[__ldg(edst + i)], 1);
}

__global__ void scan_kernel(int E) {
    __shared__ int sums[1024];
    const int tid = threadIdx.x;
    const int CH = (NODES + 1023) / 1024;
    const int beg = tid * CH;
    const int end = min(beg + CH, NODES);
    int s = 0;
    for (int i = beg; i < end; i++) s += g_count[i];
    sums[tid] = s;
    __syncthreads();
    for (int off = 1; off < 1024; off <<= 1) {
        int v = (tid >= off) ? sums[tid - off] : 0;
        __syncthreads();
        sums[tid] += v;
        __syncthreads();
    }
    int run = (tid == 0) ? 0 : sums[tid - 1];
    for (int i = beg; i < end; i++) {
        g_rowptr[i] = run;
        g_cursor[i] = run;
        run += g_count[i];
    }
    if (tid == 0) g_rowptr[NODES] = E;
}

__global__ void fill_kernel(const int* __restrict__ esrc,
                            const int* __restrict__ edst, int E) {
    int i = blockIdx.x * blockDim.x + threadIdx.x;
    if (i >= E) return;
    int d = __ldg(edst + i);
    int s = __ldg(esrc + i);
    int pos = atomicAdd(&g_cursor[d], 1);
    g_srcidx[pos] = s;
}

// ---------------------------------------------------------------------------
// Weight prep: transpose to [n][k], fp16.
// ---------------------------------------------------------------------------
__global__ void prep_weights(const float* __restrict__ W1r,
                             const float* __restrict__ W1l,
                             const float* __restrict__ W2r,
                             const float* __restrict__ W2l) {
    int b = blockIdx.x;
    int k = threadIdx.x;
    float v;
    unsigned short* dh;
    if (b < 256) {
        int n = b;
        const float* W = (n < 128) ? W1r : W1l;
        v = __ldg(W + (size_t)k * 128 + (n & 127));
        dh = g_bt1h + n * 128 + k;
    } else {
        int n = b - 256;
        const float* W = (n < 64) ? W2r : W2l;
        v = __ldg(W + (size_t)k * 64 + (n & 63));
        dh = g_bt2h + n * 128 + k;
    }
    *dh = __half_as_ushort(__float2half_rn(v));
}

// ---------------------------------------------------------------------------
// fp16x2 GEMM helpers (mma.sync.m16n8k16.f16 + ldmatrix).
// ---------------------------------------------------------------------------
#define LDKB 272   // smem bytes per 128-col fp16 row (136 * 2)

__device__ __forceinline__ uint32_t smem_u32(const void* p) {
    uint32_t a;
    asm("{ .reg .u64 t; cvta.to.shared.u64 t, %1; cvt.u32.u64 %0, t; }"
        : "=r"(a) : "l"(p));
    return a;
}

__device__ __forceinline__ void ldsm_x4(uint32_t r[4], uint32_t addr) {
    asm volatile("ldmatrix.sync.aligned.m8n8.x4.shared.b16 {%0,%1,%2,%3}, [%4];"
                 : "=r"(r[0]), "=r"(r[1]), "=r"(r[2]), "=r"(r[3]) : "r"(addr));
}

__device__ __forceinline__ void mma_f16(float c[4], const uint32_t a[4],
                                        const uint32_t b0, const uint32_t b1) {
    asm volatile(
        "mma.sync.aligned.m16n8k16.row.col.f32.f16.f16.f32 "
        "{%0,%1,%2,%3}, {%4,%5,%6,%7}, {%8,%9}, {%0,%1,%2,%3};"
        : "+f"(c[0]), "+f"(c[1]), "+f"(c[2]), "+f"(c[3])
        : "r"(a[0]), "r"(a[1]), "r"(a[2]), "r"(a[3]), "r"(b0), "r"(b1));
}

__device__ __forceinline__ uint32_t pack_half2(float a, float b) {
    __half2 h = __floats2half2_rn(a, b);
    return *reinterpret_cast<uint32_t*>(&h);
}

// ---------------------------------------------------------------------------
// gemm1: per CTA C[128 x 256] = A[128x128 fp32 -> fp16 h/l] @ Bt1^T (fp16).
// cols 0..127 -> p1 (fp32, stride 128); cols 128..255 -> t1 (fp16, stride 128).
// 8 warps 4m x 2n, warp tile 32x128. 2 passes: ah*bh + al*bh.
// ---------------------------------------------------------------------------
#define SMEM1 (2 * 128 * LDKB + 256 * LDKB)   // Ah, Al, Bh(256 rows) = 139264

__global__ void __launch_bounds__(256, 1) gemm1_tc(
    const float* __restrict__ A,
    const unsigned short* __restrict__ Bth,
    float* __restrict__ p1,
    unsigned short* __restrict__ t1,
    int Nrows) {
    extern __shared__ __align__(16) char smem[];
    constexpr int AH = 0;
    constexpr int AL = 128 * LDKB;
    constexpr int BH = 2 * 128 * LDKB;

    const int tid = threadIdx.x;
    const int row0 = blockIdx.x * 128;

    // ---- A tile: load fp32, split to fp16 hi/lo ----
#pragma unroll
    for (int i = 0; i < 16; i++) {
        int l = tid + i * 256;
        int r = l >> 5;
        int k4 = (l & 31) * 4;
        float4 v = make_float4(0.f, 0.f, 0.f, 0.f);
        int gr = row0 + r;
        if (gr < Nrows)
            v = __ldg(reinterpret_cast<const float4*>(A + (size_t)gr * 128 + k4));
        __half h0 = __float2half_rn(v.x), h1 = __float2half_rn(v.y);
        __half h2 = __float2half_rn(v.z), h3 = __float2half_rn(v.w);
        uint32_t ph0 = (uint32_t)__half_as_ushort(h0) |
                       ((uint32_t)__half_as_ushort(h1) << 16);
        uint32_t ph1 = (uint32_t)__half_as_ushort(h2) |
                       ((uint32_t)__half_as_ushort(h3) << 16);
        __half q0 = __float2half_rn(v.x - __half2float(h0));
        __half q1 = __float2half_rn(v.y - __half2float(h1));
        __half q2 = __float2half_rn(v.z - __half2float(h2));
        __half q3 = __float2half_rn(v.w - __half2float(h3));
        uint32_t pl0 = (uint32_t)__half_as_ushort(q0) |
                       ((uint32_t)__half_as_ushort(q1) << 16);
        uint32_t pl1 = (uint32_t)__half_as_ushort(q2) |
                       ((uint32_t)__half_as_ushort(q3) << 16);
        int off = r * LDKB + k4 * 2;
        *reinterpret_cast<uint2*>(smem + AH + off) = make_uint2(ph0, ph1);
        *reinterpret_cast<uint2*>(smem + AL + off) = make_uint2(pl0, pl1);
    }
    // ---- B tile: copy 256 fp16 rows ----
#pragma unroll
    for (int i = 0; i < 16; i++) {
        int l = tid + i * 256;
        int n = l >> 4;
        int k8 = (l & 15) * 8;
        uint4 vh = __ldg(reinterpret_cast<const uint4*>(Bth + (size_t)n * 128 + k8));
        *reinterpret_cast<uint4*>(smem + BH + n * LDKB + k8 * 2) = vh;
    }
    __syncthreads();

    const int wid = tid >> 5;
    const int lane = tid & 31;
    const int lane8 = lane & 7;
    const int lt = lane >> 3;
    const int gid = lane >> 2;
    const int tig = lane & 3;
    const int wm = (wid & 3) * 32;
    const int wn = (wid >> 2) * 128;

    const uint32_t sb = smem_u32(smem);
    uint32_t aoff0 = sb + (uint32_t)((wm + (lt & 1) * 8 + lane8) * LDKB +
                                     (lt >> 1) * 16);
    uint32_t boff0 = sb + BH + (uint32_t)((wn + (lt >> 1) * 8 + lane8) * LDKB +
                                          (lt & 1) * 16);

    float acc[2][16][4];
#pragma unroll
    for (int mt = 0; mt < 2; mt++)
#pragma unroll
        for (int nt = 0; nt < 16; nt++)
#pragma unroll
            for (int q = 0; q < 4; q++) acc[mt][nt][q] = 0.f;

#pragma unroll 1
    for (int ks = 0; ks < 8; ks++) {
        const uint32_t kbb = ks * 32;
        uint32_t ah[2][4], al[2][4];
#pragma unroll
        for (int mt = 0; mt < 2; mt++) {
            uint32_t a = aoff0 + mt * 16 * LDKB + kbb;
            ldsm_x4(ah[mt], a);
            ldsm_x4(al[mt], a + (AL - AH));
        }
#pragma unroll
        for (int ng = 0; ng < 8; ng++) {
            uint32_t bb[4];
            ldsm_x4(bb, boff0 + ng * 16 * LDKB + kbb);
#pragma unroll
            for (int mt = 0; mt < 2; mt++)
#pragma unroll
                for (int s = 0; s < 2; s++) {
                    int nt = ng * 2 + s;
                    mma_f16(acc[mt][nt], ah[mt], bb[s * 2], bb[s * 2 + 1]);
                    mma_f16(acc[mt][nt], al[mt], bb[s * 2], bb[s * 2 + 1]);
                }
        }
    }

    // ---- epilogue: cols <128 -> p1 fp32, cols >=128 -> t1 fp16 ----
#pragma unroll
    for (int mt = 0; mt < 2; mt++) {
#pragma unroll
        for (int nt = 0; nt < 16; nt++) {
            int jg = wn + nt * 8 + 2 * tig;
            int m0 = row0 + wm + mt * 16 + gid;
            int m1 = m0 + 8;
            if (jg < 128) {
                if (m0 < Nrows)
                    *reinterpret_cast<float2*>(p1 + (size_t)m0 * 128 + jg) =
                        make_float2(acc[mt][nt][0], acc[mt][nt][1]);
                if (m1 < Nrows)
                    *reinterpret_cast<float2*>(p1 + (size_t)m1 * 128 + jg) =
                        make_float2(acc[mt][nt][2], acc[mt][nt][3]);
            } else {
                int col = jg - 128;
                if (m0 < Nrows)
                    *reinterpret_cast<uint32_t*>(t1 + (size_t)m0 * 128 + col) =
                        pack_half2(acc[mt][nt][0], acc[mt][nt][1]);
                if (m1 < Nrows)
                    *reinterpret_cast<uint32_t*>(t1 + (size_t)m1 * 128 + col) =
                        pack_half2(acc[mt][nt][2], acc[mt][nt][3]);
            }
        }
    }
}

// ---------------------------------------------------------------------------
// gemm2: per CTA C[128 x 128] = H(presplit fp16 h/l planes) @ Bt2^T (fp16).
// cols 0..63 -> p2 (fp32, stride 64); cols 64..127 -> t2 (fp16, stride 64).
// ---------------------------------------------------------------------------
#define SMEM2 (3 * 128 * LDKB)   // Ah, Al, Bh = 104448

__global__ void __launch_bounds__(256, 2) gemm2_tc(
    const unsigned short* __restrict__ Ahh,
    const unsigned short* __restrict__ Ahl,
    const unsigned short* __restrict__ Bth,
    float* __restrict__ p2,
    unsigned short* __restrict__ t2,
    int Nrows) {
    extern __shared__ __align__(16) char smem[];
    constexpr int AH = 0;
    constexpr int AL = 128 * LDKB;
    constexpr int BH = 2 * 128 * LDKB;

    const int tid = threadIdx.x;
    const int row0 = blockIdx.x * 128;

    // ---- A tile: copy pre-split fp16 planes ----
#pragma unroll
    for (int i = 0; i < 8; i++) {
        int l = tid + i * 256;
        int r = l >> 4;
        int k8 = (l & 15) * 8;
        uint4 vh = make_uint4(0, 0, 0, 0), vl = make_uint4(0, 0, 0, 0);
        int gr = row0 + r;
        if (gr < Nrows) {
            size_t src = (size_t)gr * 128 + k8;
            vh = __ldg(reinterpret_cast<const uint4*>(Ahh + src));
            vl = __ldg(reinterpret_cast<const uint4*>(Ahl + src));
        }
        int off = r * LDKB + k8 * 2;
        *reinterpret_cast<uint4*>(smem + AH + off) = vh;
        *reinterpret_cast<uint4*>(smem + AL + off) = vl;
    }
    // ---- B tile: copy 128 fp16 rows ----
#pragma unroll
    for (int i = 0; i < 8; i++) {
        int l = tid + i * 256;
        int n = l >> 4;
        int k8 = (l & 15) * 8;
        uint4 vh = __ldg(reinterpret_cast<const uint4*>(Bth + (size_t)n * 128 + k8));
        *reinterpret_cast<uint4*>(smem + BH + n * LDKB + k8 * 2) = vh;
    }
    __syncthreads();

    const int wid = tid >> 5;
    const int lane = tid & 31;
    const int lane8 = lane & 7;
    const int lt = lane >> 3;
    const int gid = lane >> 2;
    const int tig = lane & 3;
    const int wm = (wid & 3) * 32;
    const int wn = (wid >> 2) * 64;

    const uint32_t sb = smem_u32(smem);
    uint32_t aoff0 = sb + (uint32_t)((wm + (lt & 1) * 8 + lane8) * LDKB +
                                     (lt >> 1) * 16);
    uint32_t boff0 = sb + BH + (uint32_t)((wn + (lt >> 1) * 8 + lane8) * LDKB +
                                          (lt & 1) * 16);

    float acc[2][8][4];
#pragma unroll
    for (int mt = 0; mt < 2; mt++)
#pragma unroll
        for (int nt = 0; nt < 8; nt++)
#pragma unroll
            for (int q = 0; q < 4; q++) acc[mt][nt][q] = 0.f;

#pragma unroll 2
    for (int ks = 0; ks < 8; ks++) {
        const uint32_t kbb = ks * 32;
        uint32_t ah[2][4], al[2][4];
#pragma unroll
        for (int mt = 0; mt < 2; mt++) {
            uint32_t a = aoff0 + mt * 16 * LDKB + kbb;
            ldsm_x4(ah[mt], a);
            ldsm_x4(al[mt], a + (AL - AH));
        }
#pragma unroll
        for (int ng = 0; ng < 4; ng++) {
            uint32_t bb[4];
            ldsm_x4(bb, boff0 + ng * 16 * LDKB + kbb);
#pragma unroll
            for (int mt = 0; mt < 2; mt++)
#pragma unroll
                for (int s = 0; s < 2; s++) {
                    int nt = ng * 2 + s;
                    mma_f16(acc[mt][nt], ah[mt], bb[s * 2], bb[s * 2 + 1]);
                    mma_f16(acc[mt][nt], al[mt], bb[s * 2], bb[s * 2 + 1]);
                }
        }
    }

#pragma unroll
    for (int mt = 0; mt < 2; mt++) {
#pragma unroll
        for (int nt = 0; nt < 8; nt++) {
            int jg = wn + nt * 8 + 2 * tig;
            int m0 = row0 + wm + mt * 16 + gid;
            int m1 = m0 + 8;
            if (jg < 64) {
                if (m0 < Nrows)
                    *reinterpret_cast<float2*>(p2 + (size_t)m0 * 64 + jg) =
                        make_float2(acc[mt][nt][0], acc[mt][nt][1]);
                if (m1 < Nrows)
                    *reinterpret_cast<float2*>(p2 + (size_t)m1 * 64 + jg) =
                        make_float2(acc[mt][nt][2], acc[mt][nt][3]);
            } else {
                int col = jg - 64;
                if (m0 < Nrows)
                    *reinterpret_cast<uint32_t*>(t2 + (size_t)m0 * 64 + col) =
                        pack_half2(acc[mt][nt][0], acc[mt][nt][1]);
                if (m1 < Nrows)
                    *reinterpret_cast<uint32_t*>(t2 + (size_t)m1 * 64 + col) =
                        pack_half2(acc[mt][nt][2], acc[mt][nt][3]);
            }
        }
    }
}

// ---------------------------------------------------------------------------
// gather_relu: h = relu(p1 + b1 + mean(t1[src]))  (t1 fp16) -> fp16 hi/lo.
// One warp per node in [base, limit), edge-unrolled by 8, 4 halves/lane.
// ---------------------------------------------------------------------------
__global__ void gather_relu_kernel(const unsigned short* __restrict__ t1,
                                   const float* __restrict__ p1,
                                   const float* __restrict__ bias,
                                   unsigned short* __restrict__ hh,
                                   unsigned short* __restrict__ hl,
                                   int base, int limit) {
    int w = base + (int)(((size_t)blockIdx.x * blockDim.x + threadIdx.x) >> 5);
    int lane = threadIdx.x & 31;
    if (w >= limit) return;
    int beg = __ldg(&g_rowptr[w]);
    int end = __ldg(&g_rowptr[w + 1]);
    float4 acc = make_float4(0.f, 0.f, 0.f, 0.f);
    const uint2* th = reinterpret_cast<const uint2*>(t1);  // row = 32 x uint2
    int e = beg;
    for (; e + 8 <= end; e += 8) {
        int s[8];
#pragma unroll
        for (int q = 0; q < 8; q++) s[q] = __ldg(g_srcidx + e + q);
        uint2 v[8];
#pragma unroll
        for (int q = 0; q < 8; q++) v[q] = __ldg(th + (((size_t)s[q]) << 5) + lane);
#pragma unroll
        for (int q = 0; q < 8; q++) {
            float2 f0 = __half22float2(*reinterpret_cast<__half2*>(&v[q].x));
            float2 f1 = __half22float2(*reinterpret_cast<__half2*>(&v[q].y));
            acc.x += f0.x; acc.y += f0.y; acc.z += f1.x; acc.w += f1.y;
        }
    }
    for (; e < end; e++) {
        int s = __ldg(g_srcidx + e);
        uint2 v = __ldg(th + (((size_t)s) << 5) + lane);
        float2 f0 = __half22float2(*reinterpret_cast<__half2*>(&v.x));
        float2 f1 = __half22float2(*reinterpret_cast<__half2*>(&v.y));
        acc.x += f0.x; acc.y += f0.y; acc.z += f1.x; acc.w += f1.y;
    }
    float inv = 1.0f / fmaxf((float)(end - beg), 1.0f);
    float4 p = __ldg(reinterpret_cast<const float4*>(p1) + (((size_t)w) << 5) + lane);
    float4 b = __ldg(reinterpret_cast<const float4*>(bias) + lane);
    float rx = fmaxf(fmaf(acc.x, inv, p.x + b.x), 0.f);
    float ry = fmaxf(fmaf(acc.y, inv, p.y + b.y), 0.f);
    float rz = fmaxf(fmaf(acc.z, inv, p.z + b.z), 0.f);
    float rw = fmaxf(fmaf(acc.w, inv, p.w + b.w), 0.f);
    __half h0 = __float2half_rn(rx), h1 = __float2half_rn(ry);
    __half h2 = __float2half_rn(rz), h3 = __float2half_rn(rw);
    uint32_t ph0 = (uint32_t)__half_as_ushort(h0) |
                   ((uint32_t)__half_as_ushort(h1) << 16);
    uint32_t ph1 = (uint32_t)__half_as_ushort(h2) |
                   ((uint32_t)__half_as_ushort(h3) << 16);
    __half q0 = __float2half_rn(rx - __half2float(h0));
    __half q1 = __float2half_rn(ry - __half2float(h1));
    __half q2 = __float2half_rn(rz - __half2float(h2));
    __half q3 = __float2half_rn(rw - __half2float(h3));
    uint32_t pl0 = (uint32_t)__half_as_ushort(q0) |
                   ((uint32_t)__half_as_ushort(q1) << 16);
    uint32_t pl1 = (uint32_t)__half_as_ushort(q2) |
                   ((uint32_t)__half_as_ushort(q3) << 16);
    size_t ofs = (size_t)w * 128 + lane * 4;
    *reinterpret_cast<uint2*>(hh + ofs) = make_uint2(ph0, ph1);
    *reinterpret_cast<uint2*>(hl + ofs) = make_uint2(pl0, pl1);
}

// ---------------------------------------------------------------------------
// gather_add: out = p2 + b2 + mean(t2[src])   (t2 fp16; 2 halves/lane)
// ---------------------------------------------------------------------------
__global__ void gather_add_kernel(const unsigned short* __restrict__ t2,
                                  const float* __restrict__ p2,
                                  const float* __restrict__ bias,
                                  float* __restrict__ out, int N) {
    int w = (int)(((size_t)blockIdx.x * blockDim.x + threadIdx.x) >> 5);
    int lane = threadIdx.x & 31;
    if (w >= N) return;
    int beg = __ldg(&g_rowptr[w]);
    int end = __ldg(&g_rowptr[w + 1]);
    float2 acc = make_float2(0.f, 0.f);
    const uint32_t* th = reinterpret_cast<const uint32_t*>(t2);  // row = 32 x uint
    int e = beg;
    for (; e + 8 <= end; e += 8) {
        int s[8];
#pragma unroll
        for (int q = 0; q < 8; q++) s[q] = __ldg(g_srcidx + e + q);
        uint32_t v[8];
#pragma unroll
        for (int q = 0; q < 8; q++) v[q] = __ldg(th + (((size_t)s[q]) << 5) + lane);
#pragma unroll
        for (int q = 0; q < 8; q++) {
            float2 f = __half22float2(*reinterpret_cast<__half2*>(&v[q]));
            acc.x += f.x; acc.y += f.y;
        }
    }
    for (; e < end; e++) {
        int s = __ldg(g_srcidx + e);
        uint32_t v = __ldg(th + (((size_t)s) << 5) + lane);
        float2 f = __half22float2(*reinterpret_cast<__half2*>(&v));
        acc.x += f.x; acc.y += f.y;
    }
    float inv = 1.0f / fmaxf((float)(end - beg), 1.0f);
    float2 p = __ldg(reinterpret_cast<const float2*>(p2) + (((size_t)w) << 5) + lane);
    float2 b = __ldg(reinterpret_cast<const float2*>(bias) + lane);
    float2 r;
    r.x = fmaf(acc.x, inv, p.x + b.x);
    r.y = fmaf(acc.y, inv, p.y + b.y);
    reinterpret_cast<float2*>(out)[(((size_t)w) << 5) + lane] = r;
}

// ---------------------------------------------------------------------------
// kernel_launch: CSR on side stream; gather_relu chunks pipelined with gemm2.
// ---------------------------------------------------------------------------
extern "C" void kernel_launch(void* const* d_in, const int* in_sizes, int n_in,
                              void* d_out, int out_size) {
    const float* x   = (const float*)d_in[0];
    const int*   ei  = (const int*)d_in[1];
    const float* W1l = (const float*)d_in[2];
    const float* W1r = (const float*)d_in[3];
    const float* b1  = (const float*)d_in[4];
    const float* W2l = (const float*)d_in[5];
    const float* W2r = (const float*)d_in[6];
    const float* b2  = (const float*)d_in[7];
    float* out = (float*)d_out;

    const int N = in_sizes[0] / 128;
    const int E = in_sizes[1] / 2;
    const int* esrc = ei;
    const int* edst = ei + E;

    void *pp1, *pt1, *ph, *pp2, *pt2, *b1h, *b2h;
    cudaGetSymbolAddress(&pp1, g_p1);
    cudaGetSymbolAddress(&pt1, g_t1);
    cudaGetSymbolAddress(&ph, g_h);
    cudaGetSymbolAddress(&pp2, g_p2);
    cudaGetSymbolAddress(&pt2, g_t2);
    cudaGetSymbolAddress(&b1h, g_bt1h);
    cudaGetSymbolAddress(&b2h, g_bt2h);
    float* p1 = (float*)pp1;
    unsigned short* t1 = (unsigned short*)pt1;
    float* p2 = (float*)pp2;
    unsigned short* t2 = (unsigned short*)pt2;
    unsigned short* hh = (unsigned short*)ph;              // [N][128] fp16 hi
    unsigned short* hl = hh + (size_t)NODES * 128;         // [N][128] fp16 lo
    const unsigned short* bt1h = (const unsigned short*)b1h;
    const unsigned short* bt2h = (const unsigned short*)b2h;

    static cudaStream_t side = nullptr;
    static cudaEvent_t ev_fork = nullptr, ev_join = nullptr, ev_g2 = nullptr;
    static cudaEvent_t ev_gr[4] = {nullptr, nullptr, nullptr, nullptr};
    static bool attr_set = false;
    if (!side) {
        cudaStreamCreateWithFlags(&side, cudaStreamNonBlocking);
        cudaEventCreateWithFlags(&ev_fork, cudaEventDisableTiming);
        cudaEventCreateWithFlags(&ev_join, cudaEventDisableTiming);
        cudaEventCreateWithFlags(&ev_g2, cudaEventDisableTiming);
        for (int c = 0; c < 4; c++)
            cudaEventCreateWithFlags(&ev_gr[c], cudaEventDisableTiming);
    }
    if (!attr_set) {
        cudaFuncSetAttribute(gemm1_tc,
                             cudaFuncAttributeMaxDynamicSharedMemorySize, SMEM1);
        cudaFuncSetAttribute(gemm2_tc,
                             cudaFuncAttributeMaxDynamicSharedMemorySize, SMEM2);
        attr_set = true;
    }

    const int gx = (N + 127) / 128;

    // Fork: CSR build on side stream.
    cudaEventRecord(ev_fork, 0);
    cudaStreamWaitEvent(side, ev_fork, 0);
    zero_count_kernel<<<(NODES + 255) / 256, 256, 0, side>>>();
    hist_kernel<<<(E + 255) / 256, 256, 0, side>>>(edst, E);
    scan_kernel<<<1, 1024, 0, side>>>(E);
    fill_kernel<<<(E + 255) / 256, 256, 0, side>>>(esrc, edst, E);
    cudaEventRecord(ev_join, side);

    // Weight prep + layer-1 GEMM (main stream).
    prep_weights<<<384, 128>>>(W1r, W1l, W2r, W2l);
    gemm1_tc<<<gx, 256, SMEM1>>>(x, bt1h, p1, t1, N);

    // gather_relu needs CSR.
    cudaStreamWaitEvent(0, ev_join, 0);

    // Pipelined: gather_relu chunk c (main)  ->  gemm2 chunk c (side).
    const int tpc = (gx + 3) / 4;
    for (int c = 0; c < 4; c++) {
        int t0 = c * tpc;
        if (t0 >= gx) { cudaEventRecord(ev_gr[c], 0); continue; }
        int tc = (gx - t0 < tpc) ? (gx - t0) : tpc;
        int r0 = t0 * 128;
        int rc = (N - r0 < tc * 128) ? (N - r0) : tc * 128;
        int wb = (rc * 32 + 255) / 256;
        gather_relu_kernel<<<wb, 256>>>(t1, p1, b1, hh, hl, r0, r0 + rc);
        cudaEventRecord(ev_gr[c], 0);
        cudaStreamWaitEvent(side, ev_gr[c], 0);
        gemm2_tc<<<tc, 256, SMEM2, side>>>(
            hh + (size_t)r0 * 128, hl + (size_t)r0 * 128, bt2h,
            p2 + (size_t)r0 * 64, t2 + (size_t)r0 * 64, rc);
    }
    cudaEventRecord(ev_g2, side);
    cudaStreamWaitEvent(0, ev_g2, 0);

    const int wblocks = (N * 32 + 255) / 256;
    gather_add_kernel<<<wblocks, 256>>>(t2, p2, b2, out, N);
}